// round 4
// baseline (speedup 1.0000x reference)
#include <cuda_runtime.h>
#include <math.h>

#define NR 131072
#define NBINS 2048
#define CAP 4096

// ---------------- static scratch ----------------
__device__ __align__(16) float g_h1[(size_t)NR * 512];
__device__ __align__(16) float g_h2[(size_t)NR * 256];
__device__ __align__(16) float g_nz[(size_t)NR * 16];
__device__ __align__(16) float g_nembT[16 * 256]; // [j][c]
__device__ __align__(16) float g_nembC[256 * 16]; // [c][j]
__device__ unsigned int g_hist[256 * NBINS];
__device__ unsigned int g_counts[256];
__device__ int g_thr[256 * 4]; // bt, bb, cnt_above, cnt_below
__device__ float g_topbuf[256 * CAP];
__device__ float g_botbuf[256 * CAP];
__device__ unsigned int g_topcnt[256];
__device__ unsigned int g_botcnt[256];
__device__ double g_sumexp[256];
__device__ double g_sumtop[256];
__device__ double g_acc[4]; // 0: sum(q-z)^2, 1: recon sse, 2: contra sum

// ---------------- helpers ----------------
__device__ __forceinline__ unsigned long long pk(float lo, float hi) {
    unsigned long long r; asm("mov.b64 %0,{%1,%2};" : "=l"(r) : "f"(lo), "f"(hi)); return r;
}
__device__ __forceinline__ void upk(unsigned long long v, float& lo, float& hi) {
    asm("mov.b64 {%0,%1}, %2;" : "=f"(lo), "=f"(hi) : "l"(v));
}
__device__ __forceinline__ void ffma2(unsigned long long& d, unsigned long long a, unsigned long long b) {
    asm("fma.rn.f32x2 %0, %1, %2, %3;" : "=l"(d) : "l"(a), "l"(b), "l"(d));
}
__device__ __forceinline__ float eluf(float x) { return x > 0.f ? x : expm1f(x); }
__device__ __forceinline__ float dot16(const float* a, const float* b) {
    float s = 0.f;
#pragma unroll
    for (int j = 0; j < 16; j++) s = fmaf(a[j], b[j], s);
    return s;
}
__device__ __forceinline__ int bin_of(float v) {
    int b = (int)((v + 1.0f) * (float)(NBINS / 2));
    return b < 0 ? 0 : (b > NBINS - 1 ? NBINS - 1 : b);
}
__device__ __forceinline__ float bin_low(int b) { return (float)b * (2.0f / (float)NBINS) - 1.0f; }

// ---------------- zero accumulators ----------------
__global__ void zero_kernel() {
    int i = blockIdx.x * 256 + threadIdx.x;
    if (i < 256 * NBINS) g_hist[i] = 0u;
    if (i < 256) {
        g_counts[i] = 0u; g_topcnt[i] = 0u; g_botcnt[i] = 0u;
        g_sumexp[i] = 0.0; g_sumtop[i] = 0.0;
    }
    if (i < 4) g_acc[i] = 0.0;
}

// ---------------- normalize embedding ----------------
__global__ void norm_emb_kernel(const float* __restrict__ emb) {
    int c = threadIdx.x;
    float v[16]; float ss = 0.f;
#pragma unroll
    for (int j = 0; j < 16; j++) { v[j] = emb[c * 16 + j]; ss = fmaf(v[j], v[j], ss); }
    float r = 1.0f / fmaxf(sqrtf(ss), 1e-12f);
#pragma unroll
    for (int j = 0; j < 16; j++) {
        float nv = v[j] * r;
        g_nembC[c * 16 + j] = nv;
        g_nembT[j * 256 + c] = nv;
    }
}

// ---------------- GEMM + bias + ELU, A = [A1 | A2], FFMA2 inner ----------------
__global__ void __launch_bounds__(256) gemm_bias_elu(
    const float* __restrict__ A1, int d1, const float* __restrict__ A2, int d2,
    const float* __restrict__ W, const float* __restrict__ Bv,
    float* __restrict__ C, int K, int Ncols)
{
    __shared__ __align__(16) unsigned long long As2[8][128];
    __shared__ __align__(16) float4 Bs[8][32];
    const int tid = threadIdx.x;
    const int rowBase = blockIdx.x * 128;
    const int colBase = blockIdx.y * 128;
    const int ty = tid >> 4, tx = tid & 15;
    unsigned long long acc[8][4];
#pragma unroll
    for (int i = 0; i < 8; i++)
#pragma unroll
        for (int j = 0; j < 4; j++) acc[i][j] = 0ull;

    const int aRow = rowBase + (tid >> 1);
    const int aK4 = (tid & 1) * 4;
    const int bCol = colBase + (tid & 31) * 4;
    const int bK = tid >> 5;

    for (int k0 = 0; k0 < K; k0 += 8) {
        float4 av = make_float4(0.f, 0.f, 0.f, 0.f);
        int ka = k0 + aK4;
        if (ka < K) {
            if (ka < d1) av = *(const float4*)(A1 + (size_t)aRow * d1 + ka);
            else av = *(const float4*)(A2 + (size_t)aRow * d2 + (ka - d1));
        }
        float4 bv = make_float4(0.f, 0.f, 0.f, 0.f);
        int kb = k0 + bK;
        if (kb < K) bv = *(const float4*)(W + (size_t)kb * Ncols + bCol);
        __syncthreads();
        As2[aK4 + 0][tid >> 1] = pk(av.x, av.x);
        As2[aK4 + 1][tid >> 1] = pk(av.y, av.y);
        As2[aK4 + 2][tid >> 1] = pk(av.z, av.z);
        As2[aK4 + 3][tid >> 1] = pk(av.w, av.w);
        Bs[bK][tid & 31] = bv;
        __syncthreads();
#pragma unroll
        for (int kk = 0; kk < 8; kk++) {
            const unsigned long long* ap = &As2[kk][ty * 8];
            float4 b0 = Bs[kk][tx * 2], b1 = Bs[kk][tx * 2 + 1];
            unsigned long long bp0 = pk(b0.x, b0.y), bp1 = pk(b0.z, b0.w);
            unsigned long long bp2 = pk(b1.x, b1.y), bp3 = pk(b1.z, b1.w);
#pragma unroll
            for (int i = 0; i < 8; i++) {
                unsigned long long a2 = ap[i];
                ffma2(acc[i][0], a2, bp0);
                ffma2(acc[i][1], a2, bp1);
                ffma2(acc[i][2], a2, bp2);
                ffma2(acc[i][3], a2, bp3);
            }
        }
    }
    float bias[8];
#pragma unroll
    for (int j = 0; j < 8; j++) bias[j] = Bv[colBase + tx * 8 + j];
#pragma unroll
    for (int i = 0; i < 8; i++) {
        int row = rowBase + ty * 8 + i;
        float o[8];
#pragma unroll
        for (int j = 0; j < 4; j++) upk(acc[i][j], o[j * 2], o[j * 2 + 1]);
#pragma unroll
        for (int j = 0; j < 8; j++) o[j] = eluf(o[j] + bias[j]);
        *(float4*)(C + (size_t)row * Ncols + colBase + tx * 8) = make_float4(o[0], o[1], o[2], o[3]);
        *(float4*)(C + (size_t)row * Ncols + colBase + tx * 8 + 4) = make_float4(o[4], o[5], o[6], o[7]);
    }
}

// ---------------- z head + VQ ----------------
__global__ void __launch_bounds__(256) zvq_kernel(
    const float* __restrict__ W3, const float* __restrict__ b3,
    const float* __restrict__ emb, float* __restrict__ qOut, float* __restrict__ idxOut)
{
    __shared__ __align__(16) float WsT[16 * 256];
    __shared__ __align__(16) float EsT[16 * 256];
    __shared__ float b3s[16];
    __shared__ float zsh[8][16];
    __shared__ double blkAcc;
    int tid = threadIdx.x;
    for (int i = tid; i < 4096; i += 256) { int k = i >> 4, j = i & 15; WsT[j * 256 + k] = W3[i]; }
    for (int i = tid; i < 4096; i += 256) EsT[i] = g_nembT[i];
    if (tid < 16) b3s[tid] = b3[tid];
    if (tid == 0) blkAcc = 0.0;
    __syncthreads();

    int warp = tid >> 5, lane = tid & 31;
    size_t row = (size_t)blockIdx.x * 8 + warp;
    const float4* hr = (const float4*)(g_h2 + row * 256);
    float4 h0 = hr[lane * 2], h1v = hr[lane * 2 + 1];
    float hv[8] = {h0.x, h0.y, h0.z, h0.w, h1v.x, h1v.y, h1v.z, h1v.w};
    float z[16];
#pragma unroll
    for (int j = 0; j < 16; j++) {
        const float* wj = &WsT[j * 256 + lane * 8];
        float s = 0.f;
#pragma unroll
        for (int kk = 0; kk < 8; kk++) s = fmaf(hv[kk], wj[kk], s);
        z[j] = s;
    }
#pragma unroll
    for (int off = 16; off > 0; off >>= 1)
#pragma unroll
        for (int j = 0; j < 16; j++) z[j] += __shfl_xor_sync(0xffffffffu, z[j], off);
    float ss = 0.f;
#pragma unroll
    for (int j = 0; j < 16; j++) { z[j] += b3s[j]; ss = fmaf(z[j], z[j], ss); }
    float rinv = 1.0f / fmaxf(sqrtf(ss), 1e-12f);
    float zn[16];
#pragma unroll
    for (int j = 0; j < 16; j++) zn[j] = z[j] * rinv;

    float best = -3.0e38f; int bidx = 0x7fffffff;
#pragma unroll
    for (int cc = 0; cc < 8; cc++) {
        int c = cc * 32 + lane;
        float s = 0.f;
#pragma unroll
        for (int j = 0; j < 16; j++) s = fmaf(zn[j], EsT[j * 256 + c], s);
        if (s > best) { best = s; bidx = c; }
    }
#pragma unroll
    for (int off = 16; off > 0; off >>= 1) {
        float ov = __shfl_xor_sync(0xffffffffu, best, off);
        int oi = __shfl_xor_sync(0xffffffffu, bidx, off);
        if (ov > best || (ov == best && oi < bidx)) { best = ov; bidx = oi; }
    }
    bidx = __shfl_sync(0xffffffffu, bidx, 0);
    if (lane == 0) {
        idxOut[row] = (float)bidx;
        atomicAdd(&g_counts[bidx], 1u);
#pragma unroll
        for (int j = 0; j < 16; j++) zsh[warp][j] = z[j];
    }
    __syncwarp();
    float dv = 0.f;
    if (lane < 16) {
        float q = emb[bidx * 16 + lane];
        qOut[row * 16 + lane] = q;
        g_nz[row * 16 + lane] = zn[lane];
        float d = q - zsh[warp][lane];
        dv = d * d;
    }
#pragma unroll
    for (int off = 16; off > 0; off >>= 1) dv += __shfl_xor_sync(0xffffffffu, dv, off);
    if (lane == 0) atomicAdd(&blkAcc, (double)dv);
    __syncthreads();
    if (tid == 0) atomicAdd(&g_acc[0], blkAcc);
}

// ---------------- pass A: histograms ----------------
__global__ void __launch_bounds__(256) hist_kernel() {
    __shared__ unsigned int hist[4][NBINS];
    __shared__ float cemb[4][16];
    int tid = threadIdx.x;
    for (int i = tid; i < 4 * NBINS; i += 256) ((unsigned int*)hist)[i] = 0u;
    if (tid < 64) cemb[tid >> 4][tid & 15] = g_nembC[(blockIdx.x * 4 + (tid >> 4)) * 16 + (tid & 15)];
    __syncthreads();
    size_t row0 = (size_t)blockIdx.y * 4096;
    for (int it = 0; it < 16; it++) {
        size_t row = row0 + (size_t)it * 256 + tid;
        const float4* zr = (const float4*)(g_nz + row * 16);
        float4 a = zr[0], b = zr[1], c4 = zr[2], d4 = zr[3];
        float zv[16] = {a.x, a.y, a.z, a.w, b.x, b.y, b.z, b.w, c4.x, c4.y, c4.z, c4.w, d4.x, d4.y, d4.z, d4.w};
#pragma unroll
        for (int g = 0; g < 4; g++) {
            float s = dot16(zv, cemb[g]);
            atomicAdd(&hist[g][bin_of(s)], 1u);
        }
    }
    __syncthreads();
    for (int i = tid; i < 4 * NBINS; i += 256)
        atomicAdd(&g_hist[(size_t)blockIdx.x * 4 * NBINS + i], ((unsigned int*)hist)[i]);
}

// ---------------- scan: thresholds ----------------
__global__ void __launch_bounds__(256) scan_kernel() {
    int k = blockIdx.x, tid = threadIdx.x;
    __shared__ unsigned int csum[256];
    unsigned int s = 0;
#pragma unroll
    for (int i = 0; i < 8; i++) s += g_hist[k * NBINS + tid * 8 + i];
    csum[tid] = s;
    __syncthreads();
    if (tid == 0) {
        unsigned int cum = 0; int bb = NBINS - 1; unsigned int cbelow = 0; bool done = false;
        for (int c = 0; c < 256 && !done; c++) {
            if (cum + csum[c] >= 65536u) {
                unsigned int c2 = cum;
                for (int b = c * 8; b < c * 8 + 8; b++) {
                    unsigned int h = g_hist[k * NBINS + b];
                    if (c2 + h >= 65536u) { bb = b; cbelow = c2; done = true; break; }
                    c2 += h;
                }
            } else cum += csum[c];
        }
        unsigned int cumt = 0; int bt = 0; unsigned int cabove = 0; done = false;
        for (int c = 255; c >= 0 && !done; c--) {
            if (cumt + csum[c] >= 512u) {
                unsigned int c2 = cumt;
                for (int b = c * 8 + 7; b >= c * 8; b--) {
                    unsigned int h = g_hist[k * NBINS + b];
                    if (c2 + h >= 512u) { bt = b; cabove = c2; done = true; break; }
                    c2 += h;
                }
            } else cumt += csum[c];
        }
        g_thr[k * 4 + 0] = bt; g_thr[k * 4 + 1] = bb;
        g_thr[k * 4 + 2] = (int)cabove; g_thr[k * 4 + 3] = (int)cbelow;
    }
}

// ---------------- pass B: sums + critical-bin gather ----------------
__global__ void __launch_bounds__(256) passB_kernel() {
    __shared__ float cemb[4][16];
    __shared__ int btS[4], bbS[4];
    __shared__ double dred[256];
    int tid = threadIdx.x;
    if (tid < 64) cemb[tid >> 4][tid & 15] = g_nembC[(blockIdx.x * 4 + (tid >> 4)) * 16 + (tid & 15)];
    if (tid < 4) {
        btS[tid] = g_thr[(blockIdx.x * 4 + tid) * 4 + 0];
        bbS[tid] = g_thr[(blockIdx.x * 4 + tid) * 4 + 1];
    }
    __syncthreads();
    int bt[4], bb[4]; float refv[4];
#pragma unroll
    for (int g = 0; g < 4; g++) { bt[g] = btS[g]; bb[g] = bbS[g]; refv[g] = bin_low(bt[g]); }
    double sexp[4] = {0, 0, 0, 0}, stp[4] = {0, 0, 0, 0};
    size_t row0 = (size_t)blockIdx.y * 4096;
    for (int it = 0; it < 16; it++) {
        size_t row = row0 + (size_t)it * 256 + tid;
        const float4* zr = (const float4*)(g_nz + row * 16);
        float4 a = zr[0], b = zr[1], c4 = zr[2], d4 = zr[3];
        float zv[16] = {a.x, a.y, a.z, a.w, b.x, b.y, b.z, b.w, c4.x, c4.y, c4.z, c4.w, d4.x, d4.y, d4.z, d4.w};
#pragma unroll
        for (int g = 0; g < 4; g++) {
            int k = blockIdx.x * 4 + g;
            float s = dot16(zv, cemb[g]);
            int bin = bin_of(s);
            if (bin < bb[g]) {
                sexp[g] += (double)expf((s - refv[g]) * (1.0f / 0.07f));
            } else if (bin == bb[g]) {
                unsigned int p = atomicAdd(&g_botcnt[k], 1u);
                if (p < CAP) g_botbuf[(size_t)k * CAP + p] = s;
            }
            if (bin > bt[g]) {
                stp[g] += (double)s;
            } else if (bin == bt[g]) {
                unsigned int p = atomicAdd(&g_topcnt[k], 1u);
                if (p < CAP) g_topbuf[(size_t)k * CAP + p] = s;
            }
        }
    }
#pragma unroll
    for (int g = 0; g < 4; g++) {
        dred[tid] = sexp[g]; __syncthreads();
        for (int s2 = 128; s2 > 0; s2 >>= 1) { if (tid < s2) dred[tid] += dred[tid + s2]; __syncthreads(); }
        if (tid == 0) atomicAdd(&g_sumexp[blockIdx.x * 4 + g], dred[0]);
        __syncthreads();
        dred[tid] = stp[g]; __syncthreads();
        for (int s2 = 128; s2 > 0; s2 >>= 1) { if (tid < s2) dred[tid] += dred[tid + s2]; __syncthreads(); }
        if (tid == 0) atomicAdd(&g_sumtop[blockIdx.x * 4 + g], dred[0]);
        __syncthreads();
    }
}

// ---------------- finalize: rank-select in critical bins, contra per code ----------------
__global__ void __launch_bounds__(256) finalize_kernel() {
    __shared__ float sbuf[CAP];
    __shared__ double dred[256];
    __shared__ double sh_dispos;
    int k = blockIdx.x, tid = threadIdx.x;
    int bt = g_thr[k * 4 + 0], ca = g_thr[k * 4 + 2], cb = g_thr[k * 4 + 3];
    float ref = bin_low(bt);

    int tc = min((int)g_topcnt[k], CAP);
    for (int i = tid; i < tc; i += 256) sbuf[i] = g_topbuf[(size_t)k * CAP + i];
    __syncthreads();
    int needt = 512 - ca; if (needt > tc) needt = tc; if (needt < 0) needt = 0;
    double lsum = 0.0;
    for (int i = tid; i < tc; i += 256) {
        float v = sbuf[i]; int r = 0;
        for (int j = 0; j < tc; j++) {
            float u = sbuf[j];
            r += (u > v) || (u == v && j < i);
        }
        if (r < needt) lsum += (double)v;
    }
    dred[tid] = lsum; __syncthreads();
    for (int s2 = 128; s2 > 0; s2 >>= 1) { if (tid < s2) dred[tid] += dred[tid + s2]; __syncthreads(); }
    if (tid == 0) sh_dispos = (g_sumtop[k] + dred[0]) * (1.0 / 512.0);
    __syncthreads();

    int bc = min((int)g_botcnt[k], CAP);
    for (int i = tid; i < bc; i += 256) sbuf[i] = g_botbuf[(size_t)k * CAP + i];
    __syncthreads();
    int needb = 65536 - cb; if (needb > bc) needb = bc; if (needb < 0) needb = 0;
    lsum = 0.0;
    for (int i = tid; i < bc; i += 256) {
        float v = sbuf[i]; int r = 0;
        for (int j = 0; j < bc; j++) {
            float u = sbuf[j];
            r += (u < v) || (u == v && j < i);
        }
        if (r < needb) lsum += (double)expf((v - ref) * (1.0f / 0.07f));
    }
    dred[tid] = lsum; __syncthreads();
    for (int s2 = 128; s2 > 0; s2 >>= 1) { if (tid < s2) dred[tid] += dred[tid + s2]; __syncthreads(); }
    if (tid == 0) {
        double S = (g_sumexp[k] + dred[0]) * exp(((double)ref - sh_dispos) * (1.0 / 0.07));
        atomicAdd(&g_acc[2], log1p(S));
    }
}

// ---------------- dec3 (512 -> 12) + recon loss ----------------
__global__ void __launch_bounds__(256) dec3_kernel(
    const float* __restrict__ W, const float* __restrict__ Bv,
    const float* __restrict__ actions, float* __restrict__ recOut)
{
    __shared__ __align__(16) float WsT[12][512];
    __shared__ float bs[12];
    __shared__ float rsh[8][12];
    __shared__ double blkAcc;
    int tid = threadIdx.x;
    for (int i = tid; i < 6144; i += 256) { int kk = i / 12, j = i % 12; WsT[j][kk] = W[i]; }
    if (tid < 12) bs[tid] = Bv[tid];
    if (tid == 0) blkAcc = 0.0;
    __syncthreads();
    int warp = tid >> 5, lane = tid & 31;
    size_t row = (size_t)blockIdx.x * 8 + warp;
    const float4* hp = (const float4*)(g_h1 + row * 512);
    float4 hq[4];
#pragma unroll
    for (int q = 0; q < 4; q++) hq[q] = hp[lane * 4 + q];
    float hv[16] = {hq[0].x, hq[0].y, hq[0].z, hq[0].w, hq[1].x, hq[1].y, hq[1].z, hq[1].w,
                    hq[2].x, hq[2].y, hq[2].z, hq[2].w, hq[3].x, hq[3].y, hq[3].z, hq[3].w};
#pragma unroll
    for (int j = 0; j < 12; j++) {
        const float* wj = &WsT[j][lane * 16];
        float s = 0.f;
#pragma unroll
        for (int kk = 0; kk < 16; kk++) s = fmaf(hv[kk], wj[kk], s);
#pragma unroll
        for (int off = 16; off > 0; off >>= 1) s += __shfl_xor_sync(0xffffffffu, s, off);
        if (lane == 0) rsh[warp][j] = s + bs[j];
    }
    __syncwarp();
    float dv = 0.f;
    if (lane < 12) {
        float rec = rsh[warp][lane];
        recOut[row * 12 + lane] = rec;
        float d = rec - actions[row * 12 + lane];
        dv = d * d;
    }
#pragma unroll
    for (int off = 16; off > 0; off >>= 1) dv += __shfl_xor_sync(0xffffffffu, dv, off);
    if (lane == 0) atomicAdd(&blkAcc, (double)dv);
    __syncthreads();
    if (tid == 0) atomicAdd(&g_acc[1], blkAcc);
}

// ---------------- final scalars ----------------
__global__ void final_kernel(float* __restrict__ scal) {
    __shared__ double red[256];
    int t = threadIdx.x;
    double p = (double)g_counts[t] / 131072.0;
    red[t] = p * log(p + 1e-10);
    __syncthreads();
    for (int s = 128; s > 0; s >>= 1) { if (t < s) red[t] += red[t + s]; __syncthreads(); }
    if (t == 0) {
        double q = g_acc[0] / (131072.0 * 16.0);
        scal[0] = (float)q;                               // q_latent_loss
        scal[1] = (float)(0.25 * q);                      // e_latent_loss
        scal[2] = (float)(g_acc[2] / 256.0);              // contra_loss
        scal[3] = (float)exp(-red[0]);                    // perplexity
        scal[4] = (float)(g_acc[1] / (131072.0 * 12.0));  // reconstruction_loss
    }
}

// ---------------- launch ----------------
extern "C" void kernel_launch(void* const* d_in, const int* in_sizes, int n_in,
                              void* d_out, int out_size)
{
    const float* actions = (const float*)d_in[0];
    const float* conditions = (const float*)d_in[1];
    const float* enc_w1 = (const float*)d_in[2];
    const float* enc_b1 = (const float*)d_in[3];
    const float* enc_w2 = (const float*)d_in[4];
    const float* enc_b2 = (const float*)d_in[5];
    const float* enc_w3 = (const float*)d_in[6];
    const float* enc_b3 = (const float*)d_in[7];
    const float* dec_w1 = (const float*)d_in[8];
    const float* dec_b1 = (const float*)d_in[9];
    const float* dec_w2 = (const float*)d_in[10];
    const float* dec_b2 = (const float*)d_in[11];
    const float* dec_w3 = (const float*)d_in[12];
    const float* dec_b3 = (const float*)d_in[13];
    const float* embedding = (const float*)d_in[14];

    float* out = (float*)d_out;
    float* recon = out;                       // N*12
    float* quant = out + (size_t)NR * 12;     // N*16
    float* idxf  = out + (size_t)NR * 28;     // N
    float* scal  = out + (size_t)NR * 29;     // 5 scalars

    float *h1p, *h2p;
    cudaGetSymbolAddress((void**)&h1p, g_h1);
    cudaGetSymbolAddress((void**)&h2p, g_h2);

    zero_kernel<<<2048, 256>>>();
    norm_emb_kernel<<<1, 256>>>(embedding);
    // enc1: [actions|conditions](268) @ enc_w1 -> h1 (N x 512)
    gemm_bias_elu<<<dim3(NR / 128, 4), 256>>>(actions, 12, conditions, 256, enc_w1, enc_b1, h1p, 268, 512);
    // enc2: h1(512) @ enc_w2 -> h2 (N x 256)
    gemm_bias_elu<<<dim3(NR / 128, 2), 256>>>(h1p, 512, h1p, 0, enc_w2, enc_b2, h2p, 512, 256);
    // z head + VQ
    zvq_kernel<<<NR / 8, 256>>>(enc_w3, enc_b3, embedding, quant, idxf);
    // contra stats
    hist_kernel<<<dim3(64, 32), 256>>>();
    scan_kernel<<<256, 256>>>();
    passB_kernel<<<dim3(64, 32), 256>>>();
    finalize_kernel<<<256, 256>>>();
    // dec1: [quant|conditions](272) @ dec_w1 -> h2 (N x 256)
    gemm_bias_elu<<<dim3(NR / 128, 2), 256>>>(quant, 16, conditions, 256, dec_w1, dec_b1, h2p, 272, 256);
    // dec2: h2(256) @ dec_w2 -> h1 (N x 512)
    gemm_bias_elu<<<dim3(NR / 128, 4), 256>>>(h2p, 256, h2p, 0, dec_w2, dec_b2, h1p, 256, 512);
    // dec3 + recon loss
    dec3_kernel<<<NR / 8, 256>>>(dec_w3, dec_b3, actions, recon);
    // scalars
    final_kernel<<<1, 256>>>(scal);
}

// round 7
// speedup vs baseline: 1.1913x; 1.1913x over previous
#include <cuda_runtime.h>
#include <math.h>

#define NR 131072
#define NBINS 2048
#define CAP 4096

// ---------------- static scratch ----------------
__device__ __align__(16) float g_h1[(size_t)NR * 512];
__device__ __align__(16) float g_h2[(size_t)NR * 256];
__device__ __align__(16) float g_dist[(size_t)256 * NR]; // column-major: [code][row]
__device__ __align__(16) float g_nembT[16 * 256]; // [j][c]
__device__ unsigned int g_hist[256 * NBINS];
__device__ unsigned int g_counts[256];
__device__ int g_thr[256 * 4]; // bt, bb, cnt_above, cnt_below
__device__ float g_topbuf[256 * CAP];
__device__ float g_botbuf[256 * CAP];
__device__ unsigned int g_topcnt[256];
__device__ unsigned int g_botcnt[256];
__device__ double g_sumexp[256];
__device__ double g_sumtop[256];
__device__ double g_acc[4]; // 0: sum(q-z)^2, 1: recon sse, 2: contra sum

// ---------------- helpers ----------------
__device__ __forceinline__ unsigned long long pk(float lo, float hi) {
    unsigned long long r; asm("mov.b64 %0,{%1,%2};" : "=l"(r) : "f"(lo), "f"(hi)); return r;
}
__device__ __forceinline__ void upk(unsigned long long v, float& lo, float& hi) {
    asm("mov.b64 {%0,%1}, %2;" : "=f"(lo), "=f"(hi) : "l"(v));
}
__device__ __forceinline__ void ffma2(unsigned long long& d, unsigned long long a, unsigned long long b) {
    asm("fma.rn.f32x2 %0, %1, %2, %3;" : "=l"(d) : "l"(a), "l"(b), "l"(d));
}
__device__ __forceinline__ float eluf(float x) { return x > 0.f ? x : expm1f(x); }
__device__ __forceinline__ int bin_of(float v) {
    int b = (int)((v + 1.0f) * (float)(NBINS / 2));
    return b < 0 ? 0 : (b > NBINS - 1 ? NBINS - 1 : b);
}
__device__ __forceinline__ float bin_low(int b) { return (float)b * (2.0f / (float)NBINS) - 1.0f; }

// ---------------- zero accumulators ----------------
__global__ void zero_kernel() {
    int i = threadIdx.x;
    g_counts[i] = 0u; g_topcnt[i] = 0u; g_botcnt[i] = 0u;
    if (i < 4) g_acc[i] = 0.0;
}

// ---------------- normalize embedding ----------------
__global__ void norm_emb_kernel(const float* __restrict__ emb) {
    int c = threadIdx.x;
    float v[16]; float ss = 0.f;
#pragma unroll
    for (int j = 0; j < 16; j++) { v[j] = emb[c * 16 + j]; ss = fmaf(v[j], v[j], ss); }
    float r = 1.0f / fmaxf(sqrtf(ss), 1e-12f);
#pragma unroll
    for (int j = 0; j < 16; j++) g_nembT[j * 256 + c] = v[j] * r;
}

// ---------------- GEMM + bias + ELU, A = [A1 | A2], FFMA2 inner, prefetch ----------------
__global__ void __launch_bounds__(256) gemm_bias_elu(
    const float* __restrict__ A1, int d1, const float* __restrict__ A2, int d2,
    const float* __restrict__ W, const float* __restrict__ Bv,
    float* __restrict__ C, int K, int Ncols)
{
    __shared__ __align__(16) float As[8][128];
    __shared__ __align__(16) float Bs[8][128];
    const int tid = threadIdx.x;
    const int rowBase = blockIdx.x * 128;
    const int colBase = blockIdx.y * 128;
    const int ty = tid >> 4, tx = tid & 15;
    unsigned long long acc[8][4];
#pragma unroll
    for (int i = 0; i < 8; i++)
#pragma unroll
        for (int j = 0; j < 4; j++) acc[i][j] = 0ull;

    const int aRow = rowBase + (tid >> 1);
    const int aK4 = (tid & 1) * 4;
    const int bCol = colBase + (tid & 31) * 4;
    const int bK = tid >> 5;

    float4 av = make_float4(0.f, 0.f, 0.f, 0.f);
    float4 bv = make_float4(0.f, 0.f, 0.f, 0.f);
    {
        int ka = aK4;
        if (ka < K) {
            if (ka < d1) av = *(const float4*)(A1 + (size_t)aRow * d1 + ka);
            else av = *(const float4*)(A2 + (size_t)aRow * d2 + (ka - d1));
        }
        int kb = bK;
        if (kb < K) bv = *(const float4*)(W + (size_t)kb * Ncols + bCol);
    }

    for (int k0 = 0; k0 < K; k0 += 8) {
        __syncthreads();
        As[aK4 + 0][tid >> 1] = av.x;
        As[aK4 + 1][tid >> 1] = av.y;
        As[aK4 + 2][tid >> 1] = av.z;
        As[aK4 + 3][tid >> 1] = av.w;
        *(float4*)&Bs[bK][(tid & 31) * 4] = bv;
        __syncthreads();
        // prefetch next tile into registers (hidden under compute)
        if (k0 + 8 < K) {
            av = make_float4(0.f, 0.f, 0.f, 0.f);
            bv = make_float4(0.f, 0.f, 0.f, 0.f);
            int ka = k0 + 8 + aK4;
            if (ka < K) {
                if (ka < d1) av = *(const float4*)(A1 + (size_t)aRow * d1 + ka);
                else av = *(const float4*)(A2 + (size_t)aRow * d2 + (ka - d1));
            }
            int kb = k0 + 8 + bK;
            if (kb < K) bv = *(const float4*)(W + (size_t)kb * Ncols + bCol);
        }
#pragma unroll
        for (int kk = 0; kk < 8; kk++) {
            float4 a0 = *(const float4*)&As[kk][ty * 8];
            float4 a1 = *(const float4*)&As[kk][ty * 8 + 4];
            float4 b0 = *(const float4*)&Bs[kk][tx * 8];
            float4 b1 = *(const float4*)&Bs[kk][tx * 8 + 4];
            unsigned long long bp0 = pk(b0.x, b0.y), bp1 = pk(b0.z, b0.w);
            unsigned long long bp2 = pk(b1.x, b1.y), bp3 = pk(b1.z, b1.w);
            float ar[8] = {a0.x, a0.y, a0.z, a0.w, a1.x, a1.y, a1.z, a1.w};
#pragma unroll
            for (int i = 0; i < 8; i++) {
                unsigned long long a2 = pk(ar[i], ar[i]);
                ffma2(acc[i][0], a2, bp0);
                ffma2(acc[i][1], a2, bp1);
                ffma2(acc[i][2], a2, bp2);
                ffma2(acc[i][3], a2, bp3);
            }
        }
    }
    float bias[8];
#pragma unroll
    for (int j = 0; j < 8; j++) bias[j] = Bv[colBase + tx * 8 + j];
#pragma unroll
    for (int i = 0; i < 8; i++) {
        int row = rowBase + ty * 8 + i;
        float o[8];
#pragma unroll
        for (int j = 0; j < 4; j++) upk(acc[i][j], o[j * 2], o[j * 2 + 1]);
#pragma unroll
        for (int j = 0; j < 8; j++) o[j] = eluf(o[j] + bias[j]);
        *(float4*)(C + (size_t)row * Ncols + colBase + tx * 8) = make_float4(o[0], o[1], o[2], o[3]);
        *(float4*)(C + (size_t)row * Ncols + colBase + tx * 8 + 4) = make_float4(o[4], o[5], o[6], o[7]);
    }
}

// ---------------- z head + VQ + distance matrix emit (column-major) ----------------
__global__ void __launch_bounds__(256) zvq_kernel(
    const float* __restrict__ W3, const float* __restrict__ b3,
    const float* __restrict__ emb, float* __restrict__ qOut, float* __restrict__ idxOut)
{
    __shared__ __align__(16) float WsT[16 * 256];
    __shared__ __align__(16) float EsT[16 * 256];
    __shared__ float b3s[16];
    __shared__ float zsh[8][16];
    __shared__ float dstage[256][9]; // [code][warp], padded to kill bank conflicts
    __shared__ double blkAcc;
    int tid = threadIdx.x;
    for (int i = tid; i < 4096; i += 256) { int k = i >> 4, j = i & 15; WsT[j * 256 + k] = W3[i]; }
    for (int i = tid; i < 4096; i += 256) EsT[i] = g_nembT[i];
    if (tid < 16) b3s[tid] = b3[tid];
    if (tid == 0) blkAcc = 0.0;
    __syncthreads();

    int warp = tid >> 5, lane = tid & 31;
    size_t row = (size_t)blockIdx.x * 8 + warp;
    const float4* hr = (const float4*)(g_h2 + row * 256);
    float4 h0 = hr[lane * 2], h1v = hr[lane * 2 + 1];
    float hv[8] = {h0.x, h0.y, h0.z, h0.w, h1v.x, h1v.y, h1v.z, h1v.w};
    float z[16];
#pragma unroll
    for (int j = 0; j < 16; j++) {
        const float* wj = &WsT[j * 256 + lane * 8];
        float s = 0.f;
#pragma unroll
        for (int kk = 0; kk < 8; kk++) s = fmaf(hv[kk], wj[kk], s);
        z[j] = s;
    }
#pragma unroll
    for (int off = 16; off > 0; off >>= 1)
#pragma unroll
        for (int j = 0; j < 16; j++) z[j] += __shfl_xor_sync(0xffffffffu, z[j], off);
    float ss = 0.f;
#pragma unroll
    for (int j = 0; j < 16; j++) { z[j] += b3s[j]; ss = fmaf(z[j], z[j], ss); }
    float rinv = 1.0f / fmaxf(sqrtf(ss), 1e-12f);
    float zn[16];
#pragma unroll
    for (int j = 0; j < 16; j++) zn[j] = z[j] * rinv;

    float simv[8];
    float best = -3.0e38f; int bidx = 0x7fffffff;
#pragma unroll
    for (int cc = 0; cc < 8; cc++) {
        int c = cc * 32 + lane;
        float s = 0.f;
#pragma unroll
        for (int j = 0; j < 16; j++) s = fmaf(zn[j], EsT[j * 256 + c], s);
        simv[cc] = s;
        if (s > best) { best = s; bidx = c; }
    }
#pragma unroll
    for (int cc = 0; cc < 8; cc++) dstage[cc * 32 + lane][warp] = simv[cc];
#pragma unroll
    for (int off = 16; off > 0; off >>= 1) {
        float ov = __shfl_xor_sync(0xffffffffu, best, off);
        int oi = __shfl_xor_sync(0xffffffffu, bidx, off);
        if (ov > best || (ov == best && oi < bidx)) { best = ov; bidx = oi; }
    }
    bidx = __shfl_sync(0xffffffffu, bidx, 0);
    if (lane == 0) {
        idxOut[row] = (float)bidx;
        atomicAdd(&g_counts[bidx], 1u);
#pragma unroll
        for (int j = 0; j < 16; j++) zsh[warp][j] = z[j];
    }
    __syncwarp();
    float dv = 0.f;
    if (lane < 16) {
        float q = emb[bidx * 16 + lane];
        qOut[row * 16 + lane] = q;
        float d = q - zsh[warp][lane];
        dv = d * d;
    }
#pragma unroll
    for (int off = 16; off > 0; off >>= 1) dv += __shfl_xor_sync(0xffffffffu, dv, off);
    if (lane == 0) atomicAdd(&blkAcc, (double)dv);
    __syncthreads();
    // write distances column-major: thread tid = code, 8 rows of this block
    {
        int c = tid;
        size_t row0 = (size_t)blockIdx.x * 8;
        float v[8];
#pragma unroll
        for (int i = 0; i < 8; i++) v[i] = dstage[c][i];
        float* dst = g_dist + (size_t)c * NR + row0;
        *(float4*)dst = make_float4(v[0], v[1], v[2], v[3]);
        *(float4*)(dst + 4) = make_float4(v[4], v[5], v[6], v[7]);
    }
    if (tid == 0) atomicAdd(&g_acc[0], blkAcc);
}

// ---------------- pass A: per-code histogram (1 block per code, streaming) ----------------
__global__ void __launch_bounds__(256) hist_kernel() {
    __shared__ unsigned int hist[NBINS];
    int k = blockIdx.x, tid = threadIdx.x;
    for (int i = tid; i < NBINS; i += 256) hist[i] = 0u;
    __syncthreads();
    const float4* col = (const float4*)(g_dist + (size_t)k * NR);
    for (int i = tid; i < NR / 4; i += 256) {
        float4 v = col[i];
        atomicAdd(&hist[bin_of(v.x)], 1u);
        atomicAdd(&hist[bin_of(v.y)], 1u);
        atomicAdd(&hist[bin_of(v.z)], 1u);
        atomicAdd(&hist[bin_of(v.w)], 1u);
    }
    __syncthreads();
    for (int i = tid; i < NBINS; i += 256) g_hist[k * NBINS + i] = hist[i];
}

// ---------------- scan: thresholds ----------------
__global__ void __launch_bounds__(256) scan_kernel() {
    int k = blockIdx.x, tid = threadIdx.x;
    __shared__ unsigned int csum[256];
    unsigned int s = 0;
#pragma unroll
    for (int i = 0; i < 8; i++) s += g_hist[k * NBINS + tid * 8 + i];
    csum[tid] = s;
    __syncthreads();
    if (tid == 0) {
        unsigned int cum = 0; int bb = NBINS - 1; unsigned int cbelow = 0; bool done = false;
        for (int c = 0; c < 256 && !done; c++) {
            if (cum + csum[c] >= 65536u) {
                unsigned int c2 = cum;
                for (int b = c * 8; b < c * 8 + 8; b++) {
                    unsigned int h = g_hist[k * NBINS + b];
                    if (c2 + h >= 65536u) { bb = b; cbelow = c2; done = true; break; }
                    c2 += h;
                }
            } else cum += csum[c];
        }
        unsigned int cumt = 0; int bt = 0; unsigned int cabove = 0; done = false;
        for (int c = 255; c >= 0 && !done; c--) {
            if (cumt + csum[c] >= 512u) {
                unsigned int c2 = cumt;
                for (int b = c * 8 + 7; b >= c * 8; b--) {
                    unsigned int h = g_hist[k * NBINS + b];
                    if (c2 + h >= 512u) { bt = b; cabove = c2; done = true; break; }
                    c2 += h;
                }
            } else cumt += csum[c];
        }
        g_thr[k * 4 + 0] = bt; g_thr[k * 4 + 1] = bb;
        g_thr[k * 4 + 2] = (int)cabove; g_thr[k * 4 + 3] = (int)cbelow;
    }
}

// ---------------- pass B: sums + critical-bin gather (1 block per code) ----------------
__global__ void __launch_bounds__(256) passB_kernel() {
    __shared__ double dred[256];
    int k = blockIdx.x, tid = threadIdx.x;
    int bt = g_thr[k * 4 + 0], bb = g_thr[k * 4 + 1];
    float ref = bin_low(bt);
    double sexp = 0.0, stp = 0.0;
    const float4* col = (const float4*)(g_dist + (size_t)k * NR);
    for (int i = tid; i < NR / 4; i += 256) {
        float4 v4 = col[i];
        float vs[4] = {v4.x, v4.y, v4.z, v4.w};
#pragma unroll
        for (int e = 0; e < 4; e++) {
            float s = vs[e];
            int bin = bin_of(s);
            if (bin < bb) {
                sexp += (double)expf((s - ref) * (1.0f / 0.07f));
            } else if (bin == bb) {
                unsigned int p = atomicAdd(&g_botcnt[k], 1u);
                if (p < CAP) g_botbuf[(size_t)k * CAP + p] = s;
            }
            if (bin > bt) {
                stp += (double)s;
            } else if (bin == bt) {
                unsigned int p = atomicAdd(&g_topcnt[k], 1u);
                if (p < CAP) g_topbuf[(size_t)k * CAP + p] = s;
            }
        }
    }
    dred[tid] = sexp; __syncthreads();
    for (int s2 = 128; s2 > 0; s2 >>= 1) { if (tid < s2) dred[tid] += dred[tid + s2]; __syncthreads(); }
    if (tid == 0) g_sumexp[k] = dred[0];
    __syncthreads();
    dred[tid] = stp; __syncthreads();
    for (int s2 = 128; s2 > 0; s2 >>= 1) { if (tid < s2) dred[tid] += dred[tid + s2]; __syncthreads(); }
    if (tid == 0) g_sumtop[k] = dred[0];
}

// ---------------- finalize: rank-select in critical bins, contra per code ----------------
__global__ void __launch_bounds__(256) finalize_kernel() {
    __shared__ float sbuf[CAP];
    __shared__ double dred[256];
    __shared__ double sh_dispos;
    int k = blockIdx.x, tid = threadIdx.x;
    int bt = g_thr[k * 4 + 0], ca = g_thr[k * 4 + 2], cb = g_thr[k * 4 + 3];
    float ref = bin_low(bt);

    int tc = min((int)g_topcnt[k], CAP);
    for (int i = tid; i < tc; i += 256) sbuf[i] = g_topbuf[(size_t)k * CAP + i];
    __syncthreads();
    int needt = 512 - ca; if (needt > tc) needt = tc; if (needt < 0) needt = 0;
    double lsum = 0.0;
    for (int i = tid; i < tc; i += 256) {
        float v = sbuf[i]; int r = 0;
        for (int j = 0; j < tc; j++) {
            float u = sbuf[j];
            r += (u > v) || (u == v && j < i);
        }
        if (r < needt) lsum += (double)v;
    }
    dred[tid] = lsum; __syncthreads();
    for (int s2 = 128; s2 > 0; s2 >>= 1) { if (tid < s2) dred[tid] += dred[tid + s2]; __syncthreads(); }
    if (tid == 0) sh_dispos = (g_sumtop[k] + dred[0]) * (1.0 / 512.0);
    __syncthreads();

    int bc = min((int)g_botcnt[k], CAP);
    for (int i = tid; i < bc; i += 256) sbuf[i] = g_botbuf[(size_t)k * CAP + i];
    __syncthreads();
    int needb = 65536 - cb; if (needb > bc) needb = bc; if (needb < 0) needb = 0;
    lsum = 0.0;
    for (int i = tid; i < bc; i += 256) {
        float v = sbuf[i]; int r = 0;
        for (int j = 0; j < bc; j++) {
            float u = sbuf[j];
            r += (u < v) || (u == v && j < i);
        }
        if (r < needb) lsum += (double)expf((v - ref) * (1.0f / 0.07f));
    }
    dred[tid] = lsum; __syncthreads();
    for (int s2 = 128; s2 > 0; s2 >>= 1) { if (tid < s2) dred[tid] += dred[tid + s2]; __syncthreads(); }
    if (tid == 0) {
        double S = (g_sumexp[k] + dred[0]) * exp(((double)ref - sh_dispos) * (1.0 / 0.07));
        atomicAdd(&g_acc[2], log1p(S));
    }
}

// ---------------- dec3 (512 -> 12) + recon loss ----------------
__global__ void __launch_bounds__(256) dec3_kernel(
    const float* __restrict__ W, const float* __restrict__ Bv,
    const float* __restrict__ actions, float* __restrict__ recOut)
{
    __shared__ __align__(16) float WsT[12][512];
    __shared__ float bs[12];
    __shared__ float rsh[8][12];
    __shared__ double blkAcc;
    int tid = threadIdx.x;
    for (int i = tid; i < 6144; i += 256) { int kk = i / 12, j = i % 12; WsT[j][kk] = W[i]; }
    if (tid < 12) bs[tid] = Bv[tid];
    if (tid == 0) blkAcc = 0.0;
    __syncthreads();
    int warp = tid >> 5, lane = tid & 31;
    size_t row = (size_t)blockIdx.x * 8 + warp;
    const float4* hp = (const float4*)(g_h1 + row * 512);
    float4 hq[4];
#pragma unroll
    for (int q = 0; q < 4; q++) hq[q] = hp[lane * 4 + q];
    float hv[16] = {hq[0].x, hq[0].y, hq[0].z, hq[0].w, hq[1].x, hq[1].y, hq[1].z, hq[1].w,
                    hq[2].x, hq[2].y, hq[2].z, hq[2].w, hq[3].x, hq[3].y, hq[3].z, hq[3].w};
#pragma unroll
    for (int j = 0; j < 12; j++) {
        const float* wj = &WsT[j][lane * 16];
        float s = 0.f;
#pragma unroll
        for (int kk = 0; kk < 16; kk++) s = fmaf(hv[kk], wj[kk], s);
#pragma unroll
        for (int off = 16; off > 0; off >>= 1) s += __shfl_xor_sync(0xffffffffu, s, off);
        if (lane == 0) rsh[warp][j] = s + bs[j];
    }
    __syncwarp();
    float dv = 0.f;
    if (lane < 12) {
        float rec = rsh[warp][lane];
        recOut[row * 12 + lane] = rec;
        float d = rec - actions[row * 12 + lane];
        dv = d * d;
    }
#pragma unroll
    for (int off = 16; off > 0; off >>= 1) dv += __shfl_xor_sync(0xffffffffu, dv, off);
    if (lane == 0) atomicAdd(&blkAcc, (double)dv);
    __syncthreads();
    if (tid == 0) atomicAdd(&g_acc[1], blkAcc);
}

// ---------------- final scalars ----------------
__global__ void final_kernel(float* __restrict__ scal) {
    __shared__ double red[256];
    int t = threadIdx.x;
    double p = (double)g_counts[t] / 131072.0;
    red[t] = p * log(p + 1e-10);
    __syncthreads();
    for (int s = 128; s > 0; s >>= 1) { if (t < s) red[t] += red[t + s]; __syncthreads(); }
    if (t == 0) {
        double q = g_acc[0] / (131072.0 * 16.0);
        scal[0] = (float)q;                               // q_latent_loss
        scal[1] = (float)(0.25 * q);                      // e_latent_loss
        scal[2] = (float)(g_acc[2] / 256.0);              // contra_loss
        scal[3] = (float)exp(-red[0]);                    // perplexity
        scal[4] = (float)(g_acc[1] / (131072.0 * 12.0));  // reconstruction_loss
    }
}

// ---------------- launch ----------------
extern "C" void kernel_launch(void* const* d_in, const int* in_sizes, int n_in,
                              void* d_out, int out_size)
{
    const float* actions = (const float*)d_in[0];
    const float* conditions = (const float*)d_in[1];
    const float* enc_w1 = (const float*)d_in[2];
    const float* enc_b1 = (const float*)d_in[3];
    const float* enc_w2 = (const float*)d_in[4];
    const float* enc_b2 = (const float*)d_in[5];
    const float* enc_w3 = (const float*)d_in[6];
    const float* enc_b3 = (const float*)d_in[7];
    const float* dec_w1 = (const float*)d_in[8];
    const float* dec_b1 = (const float*)d_in[9];
    const float* dec_w2 = (const float*)d_in[10];
    const float* dec_b2 = (const float*)d_in[11];
    const float* dec_w3 = (const float*)d_in[12];
    const float* dec_b3 = (const float*)d_in[13];
    const float* embedding = (const float*)d_in[14];

    float* out = (float*)d_out;
    float* recon = out;                       // N*12
    float* quant = out + (size_t)NR * 12;     // N*16
    float* idxf  = out + (size_t)NR * 28;     // N
    float* scal  = out + (size_t)NR * 29;     // 5 scalars

    float *h1p, *h2p;
    cudaGetSymbolAddress((void**)&h1p, g_h1);
    cudaGetSymbolAddress((void**)&h2p, g_h2);

    zero_kernel<<<1, 256>>>();
    norm_emb_kernel<<<1, 256>>>(embedding);
    // enc1: [actions|conditions](268) @ enc_w1 -> h1 (N x 512)
    gemm_bias_elu<<<dim3(NR / 128, 4), 256>>>(actions, 12, conditions, 256, enc_w1, enc_b1, h1p, 268, 512);
    // enc2: h1(512) @ enc_w2 -> h2 (N x 256)
    gemm_bias_elu<<<dim3(NR / 128, 2), 256>>>(h1p, 512, h1p, 0, enc_w2, enc_b2, h2p, 512, 256);
    // z head + VQ + dist emit
    zvq_kernel<<<NR / 8, 256>>>(enc_w3, enc_b3, embedding, quant, idxf);
    // contra stats (streaming over stored distances)
    hist_kernel<<<256, 256>>>();
    scan_kernel<<<256, 256>>>();
    passB_kernel<<<256, 256>>>();
    finalize_kernel<<<256, 256>>>();
    // dec1: [quant|conditions](272) @ dec_w1 -> h2 (N x 256)
    gemm_bias_elu<<<dim3(NR / 128, 2), 256>>>(quant, 16, conditions, 256, dec_w1, dec_b1, h2p, 272, 256);
    // dec2: h2(256) @ dec_w2 -> h1 (N x 512)
    gemm_bias_elu<<<dim3(NR / 128, 4), 256>>>(h2p, 256, h2p, 0, dec_w2, dec_b2, h1p, 256, 512);
    // dec3 + recon loss
    dec3_kernel<<<NR / 8, 256>>>(dec_w3, dec_b3, actions, recon);
    // scalars
    final_kernel<<<1, 256>>>(scal);
}

// round 8
// speedup vs baseline: 1.2458x; 1.0458x over previous
#include <cuda_runtime.h>
#include <math.h>

#define NR 131072
#define NBINS 2048
#define CAP 4096

// ---------------- static scratch ----------------
__device__ __align__(16) float g_h1[(size_t)NR * 512];
__device__ __align__(16) float g_h2[(size_t)NR * 256];
__device__ __align__(16) float g_dist[(size_t)256 * NR]; // column-major: [code][row]
__device__ __align__(16) float g_nembT[16 * 256]; // [j][c]
__device__ unsigned int g_hist[256 * NBINS];
__device__ unsigned int g_counts[256];
__device__ int g_thr[256 * 4]; // bt, bb, cnt_above, cnt_below
__device__ float g_topbuf[256 * CAP];
__device__ float g_botbuf[256 * CAP];
__device__ unsigned int g_topcnt[256];
__device__ unsigned int g_botcnt[256];
__device__ double g_sumexp[256];
__device__ double g_sumtop[256];
__device__ double g_acc[4]; // 0: sum(q-z)^2, 1: recon sse, 2: contra sum

// ---------------- helpers ----------------
__device__ __forceinline__ unsigned long long pk(float lo, float hi) {
    unsigned long long r; asm("mov.b64 %0,{%1,%2};" : "=l"(r) : "f"(lo), "f"(hi)); return r;
}
__device__ __forceinline__ void upk(unsigned long long v, float& lo, float& hi) {
    asm("mov.b64 {%0,%1}, %2;" : "=f"(lo), "=f"(hi) : "l"(v));
}
__device__ __forceinline__ void ffma2(unsigned long long& d, unsigned long long a, unsigned long long b) {
    asm("fma.rn.f32x2 %0, %1, %2, %3;" : "=l"(d) : "l"(a), "l"(b), "l"(d));
}
__device__ __forceinline__ float eluf(float x) { return x > 0.f ? x : expm1f(x); }
__device__ __forceinline__ int bin_of(float v) {
    int b = (int)((v + 1.0f) * (float)(NBINS / 2));
    return b < 0 ? 0 : (b > NBINS - 1 ? NBINS - 1 : b);
}
__device__ __forceinline__ float bin_low(int b) { return (float)b * (2.0f / (float)NBINS) - 1.0f; }

// ---------------- zero accumulators ----------------
__global__ void zero_kernel() {
    int i = threadIdx.x;
    g_counts[i] = 0u; g_topcnt[i] = 0u; g_botcnt[i] = 0u;
    if (i < 4) g_acc[i] = 0.0;
}

// ---------------- normalize embedding ----------------
__global__ void norm_emb_kernel(const float* __restrict__ emb) {
    int c = threadIdx.x;
    float v[16]; float ss = 0.f;
#pragma unroll
    for (int j = 0; j < 16; j++) { v[j] = emb[c * 16 + j]; ss = fmaf(v[j], v[j], ss); }
    float r = 1.0f / fmaxf(sqrtf(ss), 1e-12f);
#pragma unroll
    for (int j = 0; j < 16; j++) g_nembT[j * 256 + c] = v[j] * r;
}

// ---------------- GEMM + bias + ELU, A = [A1 | A2], FFMA2, double-buffered smem ----------------
__global__ void __launch_bounds__(256) gemm_bias_elu(
    const float* __restrict__ A1, int d1, const float* __restrict__ A2, int d2,
    const float* __restrict__ W, const float* __restrict__ Bv,
    float* __restrict__ C, int K, int Ncols)
{
    __shared__ __align__(16) float As[2][8][128];
    __shared__ __align__(16) float Bs[2][8][128];
    const int tid = threadIdx.x;
    const int rowBase = blockIdx.x * 128;
    const int colBase = blockIdx.y * 128;
    const int ty = tid >> 4, tx = tid & 15;
    unsigned long long acc[8][4];
#pragma unroll
    for (int i = 0; i < 8; i++)
#pragma unroll
        for (int j = 0; j < 4; j++) acc[i][j] = 0ull;

    const int aRow = rowBase + (tid >> 1);
    const int aK4 = (tid & 1) * 4;
    const int bCol = colBase + (tid & 31) * 4;
    const int bK = tid >> 5;

    // load tile 0
    float4 av = make_float4(0.f, 0.f, 0.f, 0.f);
    float4 bv = make_float4(0.f, 0.f, 0.f, 0.f);
    {
        int ka = aK4;
        if (ka < K) {
            if (ka < d1) av = *(const float4*)(A1 + (size_t)aRow * d1 + ka);
            else av = *(const float4*)(A2 + (size_t)aRow * d2 + (ka - d1));
        }
        int kb = bK;
        if (kb < K) bv = *(const float4*)(W + (size_t)kb * Ncols + bCol);
    }
    As[0][aK4 + 0][tid >> 1] = av.x;
    As[0][aK4 + 1][tid >> 1] = av.y;
    As[0][aK4 + 2][tid >> 1] = av.z;
    As[0][aK4 + 3][tid >> 1] = av.w;
    *(float4*)&Bs[0][bK][(tid & 31) * 4] = bv;
    __syncthreads();

    int buf = 0;
    for (int k0 = 0; k0 < K; k0 += 8) {
        const bool more = (k0 + 8 < K);
        // prefetch next tile into registers (in flight during compute)
        if (more) {
            av = make_float4(0.f, 0.f, 0.f, 0.f);
            bv = make_float4(0.f, 0.f, 0.f, 0.f);
            int ka = k0 + 8 + aK4;
            if (ka < K) {
                if (ka < d1) av = *(const float4*)(A1 + (size_t)aRow * d1 + ka);
                else av = *(const float4*)(A2 + (size_t)aRow * d2 + (ka - d1));
            }
            int kb = k0 + 8 + bK;
            if (kb < K) bv = *(const float4*)(W + (size_t)kb * Ncols + bCol);
        }
#pragma unroll
        for (int kk = 0; kk < 8; kk++) {
            float4 a0 = *(const float4*)&As[buf][kk][ty * 8];
            float4 a1 = *(const float4*)&As[buf][kk][ty * 8 + 4];
            float4 b0 = *(const float4*)&Bs[buf][kk][tx * 8];
            float4 b1 = *(const float4*)&Bs[buf][kk][tx * 8 + 4];
            unsigned long long bp0 = pk(b0.x, b0.y), bp1 = pk(b0.z, b0.w);
            unsigned long long bp2 = pk(b1.x, b1.y), bp3 = pk(b1.z, b1.w);
            float ar[8] = {a0.x, a0.y, a0.z, a0.w, a1.x, a1.y, a1.z, a1.w};
#pragma unroll
            for (int i = 0; i < 8; i++) {
                unsigned long long a2 = pk(ar[i], ar[i]);
                ffma2(acc[i][0], a2, bp0);
                ffma2(acc[i][1], a2, bp1);
                ffma2(acc[i][2], a2, bp2);
                ffma2(acc[i][3], a2, bp3);
            }
        }
        if (more) {
            int nb = buf ^ 1;
            As[nb][aK4 + 0][tid >> 1] = av.x;
            As[nb][aK4 + 1][tid >> 1] = av.y;
            As[nb][aK4 + 2][tid >> 1] = av.z;
            As[nb][aK4 + 3][tid >> 1] = av.w;
            *(float4*)&Bs[nb][bK][(tid & 31) * 4] = bv;
            __syncthreads();
            buf = nb;
        }
    }
    float bias[8];
#pragma unroll
    for (int j = 0; j < 8; j++) bias[j] = Bv[colBase + tx * 8 + j];
#pragma unroll
    for (int i = 0; i < 8; i++) {
        int row = rowBase + ty * 8 + i;
        float o[8];
#pragma unroll
        for (int j = 0; j < 4; j++) upk(acc[i][j], o[j * 2], o[j * 2 + 1]);
#pragma unroll
        for (int j = 0; j < 8; j++) o[j] = eluf(o[j] + bias[j]);
        *(float4*)(C + (size_t)row * Ncols + colBase + tx * 8) = make_float4(o[0], o[1], o[2], o[3]);
        *(float4*)(C + (size_t)row * Ncols + colBase + tx * 8 + 4) = make_float4(o[4], o[5], o[6], o[7]);
    }
}

// ---------------- z head + VQ + distance matrix emit (column-major) ----------------
__global__ void __launch_bounds__(256) zvq_kernel(
    const float* __restrict__ W3, const float* __restrict__ b3,
    const float* __restrict__ emb, float* __restrict__ qOut, float* __restrict__ idxOut)
{
    __shared__ __align__(16) float WsT[16 * 256];
    __shared__ __align__(16) float EsT[16 * 256];
    __shared__ float b3s[16];
    __shared__ float zsh[8][16];
    __shared__ float dstage[256][9]; // [code][warp], padded to kill bank conflicts
    __shared__ double blkAcc;
    int tid = threadIdx.x;
    for (int i = tid; i < 4096; i += 256) { int k = i >> 4, j = i & 15; WsT[j * 256 + k] = W3[i]; }
    for (int i = tid; i < 4096; i += 256) EsT[i] = g_nembT[i];
    if (tid < 16) b3s[tid] = b3[tid];
    if (tid == 0) blkAcc = 0.0;
    __syncthreads();

    int warp = tid >> 5, lane = tid & 31;
    size_t row = (size_t)blockIdx.x * 8 + warp;
    const float4* hr = (const float4*)(g_h2 + row * 256);
    float4 h0 = hr[lane * 2], h1v = hr[lane * 2 + 1];
    float hv[8] = {h0.x, h0.y, h0.z, h0.w, h1v.x, h1v.y, h1v.z, h1v.w};
    float z[16];
#pragma unroll
    for (int j = 0; j < 16; j++) {
        const float* wj = &WsT[j * 256 + lane * 8];
        float s = 0.f;
#pragma unroll
        for (int kk = 0; kk < 8; kk++) s = fmaf(hv[kk], wj[kk], s);
        z[j] = s;
    }
#pragma unroll
    for (int off = 16; off > 0; off >>= 1)
#pragma unroll
        for (int j = 0; j < 16; j++) z[j] += __shfl_xor_sync(0xffffffffu, z[j], off);
    float ss = 0.f;
#pragma unroll
    for (int j = 0; j < 16; j++) { z[j] += b3s[j]; ss = fmaf(z[j], z[j], ss); }
    float rinv = 1.0f / fmaxf(sqrtf(ss), 1e-12f);
    float zn[16];
#pragma unroll
    for (int j = 0; j < 16; j++) zn[j] = z[j] * rinv;

    float simv[8];
    float best = -3.0e38f; int bidx = 0x7fffffff;
#pragma unroll
    for (int cc = 0; cc < 8; cc++) {
        int c = cc * 32 + lane;
        float s = 0.f;
#pragma unroll
        for (int j = 0; j < 16; j++) s = fmaf(zn[j], EsT[j * 256 + c], s);
        simv[cc] = s;
        if (s > best) { best = s; bidx = c; }
    }
#pragma unroll
    for (int cc = 0; cc < 8; cc++) dstage[cc * 32 + lane][warp] = simv[cc];
#pragma unroll
    for (int off = 16; off > 0; off >>= 1) {
        float ov = __shfl_xor_sync(0xffffffffu, best, off);
        int oi = __shfl_xor_sync(0xffffffffu, bidx, off);
        if (ov > best || (ov == best && oi < bidx)) { best = ov; bidx = oi; }
    }
    bidx = __shfl_sync(0xffffffffu, bidx, 0);
    if (lane == 0) {
        idxOut[row] = (float)bidx;
        atomicAdd(&g_counts[bidx], 1u);
#pragma unroll
        for (int j = 0; j < 16; j++) zsh[warp][j] = z[j];
    }
    __syncwarp();
    float dv = 0.f;
    if (lane < 16) {
        float q = emb[bidx * 16 + lane];
        qOut[row * 16 + lane] = q;
        float d = q - zsh[warp][lane];
        dv = d * d;
    }
#pragma unroll
    for (int off = 16; off > 0; off >>= 1) dv += __shfl_xor_sync(0xffffffffu, dv, off);
    if (lane == 0) atomicAdd(&blkAcc, (double)dv);
    __syncthreads();
    // write distances column-major: thread tid = code, 8 rows of this block
    {
        int c = tid;
        size_t row0 = (size_t)blockIdx.x * 8;
        float v[8];
#pragma unroll
        for (int i = 0; i < 8; i++) v[i] = dstage[c][i];
        float* dst = g_dist + (size_t)c * NR + row0;
        *(float4*)dst = make_float4(v[0], v[1], v[2], v[3]);
        *(float4*)(dst + 4) = make_float4(v[4], v[5], v[6], v[7]);
    }
    if (tid == 0) atomicAdd(&g_acc[0], blkAcc);
}

// ---------------- pass A: per-code histogram (1 block per code, streaming) ----------------
__global__ void __launch_bounds__(256) hist_kernel() {
    __shared__ unsigned int hist[NBINS];
    int k = blockIdx.x, tid = threadIdx.x;
    for (int i = tid; i < NBINS; i += 256) hist[i] = 0u;
    __syncthreads();
    const float4* col = (const float4*)(g_dist + (size_t)k * NR);
    for (int i = tid; i < NR / 4; i += 256) {
        float4 v = col[i];
        atomicAdd(&hist[bin_of(v.x)], 1u);
        atomicAdd(&hist[bin_of(v.y)], 1u);
        atomicAdd(&hist[bin_of(v.z)], 1u);
        atomicAdd(&hist[bin_of(v.w)], 1u);
    }
    __syncthreads();
    for (int i = tid; i < NBINS; i += 256) g_hist[k * NBINS + i] = hist[i];
}

// ---------------- scan: thresholds ----------------
__global__ void __launch_bounds__(256) scan_kernel() {
    int k = blockIdx.x, tid = threadIdx.x;
    __shared__ unsigned int csum[256];
    unsigned int s = 0;
#pragma unroll
    for (int i = 0; i < 8; i++) s += g_hist[k * NBINS + tid * 8 + i];
    csum[tid] = s;
    __syncthreads();
    if (tid == 0) {
        unsigned int cum = 0; int bb = NBINS - 1; unsigned int cbelow = 0; bool done = false;
        for (int c = 0; c < 256 && !done; c++) {
            if (cum + csum[c] >= 65536u) {
                unsigned int c2 = cum;
                for (int b = c * 8; b < c * 8 + 8; b++) {
                    unsigned int h = g_hist[k * NBINS + b];
                    if (c2 + h >= 65536u) { bb = b; cbelow = c2; done = true; break; }
                    c2 += h;
                }
            } else cum += csum[c];
        }
        unsigned int cumt = 0; int bt = 0; unsigned int cabove = 0; done = false;
        for (int c = 255; c >= 0 && !done; c--) {
            if (cumt + csum[c] >= 512u) {
                unsigned int c2 = cumt;
                for (int b = c * 8 + 7; b >= c * 8; b--) {
                    unsigned int h = g_hist[k * NBINS + b];
                    if (c2 + h >= 512u) { bt = b; cabove = c2; done = true; break; }
                    c2 += h;
                }
            } else cumt += csum[c];
        }
        g_thr[k * 4 + 0] = bt; g_thr[k * 4 + 1] = bb;
        g_thr[k * 4 + 2] = (int)cabove; g_thr[k * 4 + 3] = (int)cbelow;
    }
}

// ---------------- pass B: sums + critical-bin gather (1 block per code) ----------------
__global__ void __launch_bounds__(256) passB_kernel() {
    __shared__ double dred[256];
    int k = blockIdx.x, tid = threadIdx.x;
    int bt = g_thr[k * 4 + 0], bb = g_thr[k * 4 + 1];
    float ref = bin_low(bt);
    double sexp = 0.0, stp = 0.0;
    const float4* col = (const float4*)(g_dist + (size_t)k * NR);
    for (int i = tid; i < NR / 4; i += 256) {
        float4 v4 = col[i];
        float vs[4] = {v4.x, v4.y, v4.z, v4.w};
#pragma unroll
        for (int e = 0; e < 4; e++) {
            float s = vs[e];
            int bin = bin_of(s);
            if (bin < bb) {
                sexp += (double)expf((s - ref) * (1.0f / 0.07f));
            } else if (bin == bb) {
                unsigned int p = atomicAdd(&g_botcnt[k], 1u);
                if (p < CAP) g_botbuf[(size_t)k * CAP + p] = s;
            }
            if (bin > bt) {
                stp += (double)s;
            } else if (bin == bt) {
                unsigned int p = atomicAdd(&g_topcnt[k], 1u);
                if (p < CAP) g_topbuf[(size_t)k * CAP + p] = s;
            }
        }
    }
    dred[tid] = sexp; __syncthreads();
    for (int s2 = 128; s2 > 0; s2 >>= 1) { if (tid < s2) dred[tid] += dred[tid + s2]; __syncthreads(); }
    if (tid == 0) g_sumexp[k] = dred[0];
    __syncthreads();
    dred[tid] = stp; __syncthreads();
    for (int s2 = 128; s2 > 0; s2 >>= 1) { if (tid < s2) dred[tid] += dred[tid + s2]; __syncthreads(); }
    if (tid == 0) g_sumtop[k] = dred[0];
}

// ---------------- finalize: rank-select in critical bins, contra per code ----------------
__global__ void __launch_bounds__(256) finalize_kernel() {
    __shared__ float sbuf[CAP];
    __shared__ double dred[256];
    __shared__ double sh_dispos;
    int k = blockIdx.x, tid = threadIdx.x;
    int bt = g_thr[k * 4 + 0], ca = g_thr[k * 4 + 2], cb = g_thr[k * 4 + 3];
    float ref = bin_low(bt);

    int tc = min((int)g_topcnt[k], CAP);
    for (int i = tid; i < tc; i += 256) sbuf[i] = g_topbuf[(size_t)k * CAP + i];
    __syncthreads();
    int needt = 512 - ca; if (needt > tc) needt = tc; if (needt < 0) needt = 0;
    double lsum = 0.0;
    for (int i = tid; i < tc; i += 256) {
        float v = sbuf[i]; int r = 0;
        for (int j = 0; j < tc; j++) {
            float u = sbuf[j];
            r += (u > v) || (u == v && j < i);
        }
        if (r < needt) lsum += (double)v;
    }
    dred[tid] = lsum; __syncthreads();
    for (int s2 = 128; s2 > 0; s2 >>= 1) { if (tid < s2) dred[tid] += dred[tid + s2]; __syncthreads(); }
    if (tid == 0) sh_dispos = (g_sumtop[k] + dred[0]) * (1.0 / 512.0);
    __syncthreads();

    int bc = min((int)g_botcnt[k], CAP);
    for (int i = tid; i < bc; i += 256) sbuf[i] = g_botbuf[(size_t)k * CAP + i];
    __syncthreads();
    int needb = 65536 - cb; if (needb > bc) needb = bc; if (needb < 0) needb = 0;
    lsum = 0.0;
    for (int i = tid; i < bc; i += 256) {
        float v = sbuf[i]; int r = 0;
        for (int j = 0; j < bc; j++) {
            float u = sbuf[j];
            r += (u < v) || (u == v && j < i);
        }
        if (r < needb) lsum += (double)expf((v - ref) * (1.0f / 0.07f));
    }
    dred[tid] = lsum; __syncthreads();
    for (int s2 = 128; s2 > 0; s2 >>= 1) { if (tid < s2) dred[tid] += dred[tid + s2]; __syncthreads(); }
    if (tid == 0) {
        double S = (g_sumexp[k] + dred[0]) * exp(((double)ref - sh_dispos) * (1.0 / 0.07));
        atomicAdd(&g_acc[2], log1p(S));
    }
}

// ---------------- dec3 (512 -> 12) + recon loss ----------------
__global__ void __launch_bounds__(256) dec3_kernel(
    const float* __restrict__ W, const float* __restrict__ Bv,
    const float* __restrict__ actions, float* __restrict__ recOut)
{
    __shared__ __align__(16) float WsT[12][512];
    __shared__ float bs[12];
    __shared__ float rsh[8][12];
    __shared__ double blkAcc;
    int tid = threadIdx.x;
    for (int i = tid; i < 6144; i += 256) { int kk = i / 12, j = i % 12; WsT[j][kk] = W[i]; }
    if (tid < 12) bs[tid] = Bv[tid];
    if (tid == 0) blkAcc = 0.0;
    __syncthreads();
    int warp = tid >> 5, lane = tid & 31;
    size_t row = (size_t)blockIdx.x * 8 + warp;
    const float4* hp = (const float4*)(g_h1 + row * 512);
    float4 hq[4];
#pragma unroll
    for (int q = 0; q < 4; q++) hq[q] = hp[lane * 4 + q];
    float hv[16] = {hq[0].x, hq[0].y, hq[0].z, hq[0].w, hq[1].x, hq[1].y, hq[1].z, hq[1].w,
                    hq[2].x, hq[2].y, hq[2].z, hq[2].w, hq[3].x, hq[3].y, hq[3].z, hq[3].w};
#pragma unroll
    for (int j = 0; j < 12; j++) {
        const float* wj = &WsT[j][lane * 16];
        float s = 0.f;
#pragma unroll
        for (int kk = 0; kk < 16; kk++) s = fmaf(hv[kk], wj[kk], s);
#pragma unroll
        for (int off = 16; off > 0; off >>= 1) s += __shfl_xor_sync(0xffffffffu, s, off);
        if (lane == 0) rsh[warp][j] = s + bs[j];
    }
    __syncwarp();
    float dv = 0.f;
    if (lane < 12) {
        float rec = rsh[warp][lane];
        recOut[row * 12 + lane] = rec;
        float d = rec - actions[row * 12 + lane];
        dv = d * d;
    }
#pragma unroll
    for (int off = 16; off > 0; off >>= 1) dv += __shfl_xor_sync(0xffffffffu, dv, off);
    if (lane == 0) atomicAdd(&blkAcc, (double)dv);
    __syncthreads();
    if (tid == 0) atomicAdd(&g_acc[1], blkAcc);
}

// ---------------- final scalars ----------------
__global__ void final_kernel(float* __restrict__ scal) {
    __shared__ double red[256];
    int t = threadIdx.x;
    double p = (double)g_counts[t] / 131072.0;
    red[t] = p * log(p + 1e-10);
    __syncthreads();
    for (int s = 128; s > 0; s >>= 1) { if (t < s) red[t] += red[t + s]; __syncthreads(); }
    if (t == 0) {
        double q = g_acc[0] / (131072.0 * 16.0);
        scal[0] = (float)q;                               // q_latent_loss
        scal[1] = (float)(0.25 * q);                      // e_latent_loss
        scal[2] = (float)(g_acc[2] / 256.0);              // contra_loss
        scal[3] = (float)exp(-red[0]);                    // perplexity
        scal[4] = (float)(g_acc[1] / (131072.0 * 12.0));  // reconstruction_loss
    }
}

// ---------------- launch ----------------
extern "C" void kernel_launch(void* const* d_in, const int* in_sizes, int n_in,
                              void* d_out, int out_size)
{
    const float* actions = (const float*)d_in[0];
    const float* conditions = (const float*)d_in[1];
    const float* enc_w1 = (const float*)d_in[2];
    const float* enc_b1 = (const float*)d_in[3];
    const float* enc_w2 = (const float*)d_in[4];
    const float* enc_b2 = (const float*)d_in[5];
    const float* enc_w3 = (const float*)d_in[6];
    const float* enc_b3 = (const float*)d_in[7];
    const float* dec_w1 = (const float*)d_in[8];
    const float* dec_b1 = (const float*)d_in[9];
    const float* dec_w2 = (const float*)d_in[10];
    const float* dec_b2 = (const float*)d_in[11];
    const float* dec_w3 = (const float*)d_in[12];
    const float* dec_b3 = (const float*)d_in[13];
    const float* embedding = (const float*)d_in[14];

    float* out = (float*)d_out;
    float* recon = out;                       // N*12
    float* quant = out + (size_t)NR * 12;     // N*16
    float* idxf  = out + (size_t)NR * 28;     // N
    float* scal  = out + (size_t)NR * 29;     // 5 scalars

    float *h1p, *h2p;
    cudaGetSymbolAddress((void**)&h1p, g_h1);
    cudaGetSymbolAddress((void**)&h2p, g_h2);

    zero_kernel<<<1, 256>>>();
    norm_emb_kernel<<<1, 256>>>(embedding);
    // enc1: [actions|conditions](268) @ enc_w1 -> h1 (N x 512)
    gemm_bias_elu<<<dim3(NR / 128, 4), 256>>>(actions, 12, conditions, 256, enc_w1, enc_b1, h1p, 268, 512);
    // enc2: h1(512) @ enc_w2 -> h2 (N x 256)
    gemm_bias_elu<<<dim3(NR / 128, 2), 256>>>(h1p, 512, h1p, 0, enc_w2, enc_b2, h2p, 512, 256);
    // z head + VQ + dist emit
    zvq_kernel<<<NR / 8, 256>>>(enc_w3, enc_b3, embedding, quant, idxf);
    // contra stats (streaming over stored distances)
    hist_kernel<<<256, 256>>>();
    scan_kernel<<<256, 256>>>();
    passB_kernel<<<256, 256>>>();
    finalize_kernel<<<256, 256>>>();
    // dec1: [quant|conditions](272) @ dec_w1 -> h2 (N x 256)
    gemm_bias_elu<<<dim3(NR / 128, 2), 256>>>(quant, 16, conditions, 256, dec_w1, dec_b1, h2p, 272, 256);
    // dec2: h2(256) @ dec_w2 -> h1 (N x 512)
    gemm_bias_elu<<<dim3(NR / 128, 4), 256>>>(h2p, 256, h2p, 0, dec_w2, dec_b2, h1p, 256, 512);
    // dec3 + recon loss
    dec3_kernel<<<NR / 8, 256>>>(dec_w3, dec_b3, actions, recon);
    // scalars
    final_kernel<<<1, 256>>>(scal);
}

// round 13
// speedup vs baseline: 1.3983x; 1.1224x over previous
#include <cuda_runtime.h>
#include <math.h>

#define NR 131072
#define NBINS 2048
#define CAP 4096

// ---------------- static scratch ----------------
__device__ __align__(16) float g_h1[(size_t)NR * 512];
__device__ __align__(16) float g_h2[(size_t)NR * 256];
__device__ __align__(16) float g_dist[(size_t)256 * NR]; // column-major: [code][row]
__device__ __align__(16) float g_nembT[16 * 256]; // [j][c]
__device__ unsigned int g_hist[256 * NBINS];
__device__ unsigned int g_counts[256];
__device__ int g_thr[256 * 4]; // bt, bb, cnt_above, cnt_below
__device__ float g_topbuf[256 * CAP];
__device__ float g_botbuf[256 * CAP];
__device__ unsigned int g_topcnt[256];
__device__ unsigned int g_botcnt[256];
__device__ double g_sumexp[256];
__device__ double g_sumtop[256];
__device__ double g_acc[4]; // 0: sum(q-z)^2, 1: recon sse, 2: contra sum

// ---------------- helpers ----------------
__device__ __forceinline__ unsigned long long pk(float lo, float hi) {
    unsigned long long r; asm("mov.b64 %0,{%1,%2};" : "=l"(r) : "f"(lo), "f"(hi)); return r;
}
__device__ __forceinline__ void upk(unsigned long long v, float& lo, float& hi) {
    asm("mov.b64 {%0,%1}, %2;" : "=f"(lo), "=f"(hi) : "l"(v));
}
__device__ __forceinline__ void ffma2(unsigned long long& d, unsigned long long a, unsigned long long b) {
    asm("fma.rn.f32x2 %0, %1, %2, %3;" : "=l"(d) : "l"(a), "l"(b), "l"(d));
}
__device__ __forceinline__ float eluf(float x) { return x > 0.f ? x : expm1f(x); }
__device__ __forceinline__ int bin_of(float v) {
    int b = (int)((v + 1.0f) * (float)(NBINS / 2));
    return b < 0 ? 0 : (b > NBINS - 1 ? NBINS - 1 : b);
}
__device__ __forceinline__ float bin_low(int b) { return (float)b * (2.0f / (float)NBINS) - 1.0f; }

// ---------------- zero accumulators (hist + scalars) ----------------
__global__ void zero_kernel() {
    int i = blockIdx.x * 256 + threadIdx.x;
    if (i < 256 * NBINS) g_hist[i] = 0u;
    if (i < 256) {
        g_counts[i] = 0u; g_topcnt[i] = 0u; g_botcnt[i] = 0u;
        g_sumexp[i] = 0.0; g_sumtop[i] = 0.0;
    }
    if (i < 4) g_acc[i] = 0.0;
}

// ---------------- normalize embedding ----------------
__global__ void norm_emb_kernel(const float* __restrict__ emb) {
    int c = threadIdx.x;
    float v[16]; float ss = 0.f;
#pragma unroll
    for (int j = 0; j < 16; j++) { v[j] = emb[c * 16 + j]; ss = fmaf(v[j], v[j], ss); }
    float r = 1.0f / fmaxf(sqrtf(ss), 1e-12f);
#pragma unroll
    for (int j = 0; j < 16; j++) g_nembT[j * 256 + c] = v[j] * r;
}

// ---------------- GEMM + bias + ELU, A = [A1 | A2], FFMA2, double-buffered,
//                  conflict-free B fragment mapping (cols tx*4 and 64+tx*4) ----------------
__global__ void __launch_bounds__(256) gemm_bias_elu(
    const float* __restrict__ A1, int d1, const float* __restrict__ A2, int d2,
    const float* __restrict__ W, const float* __restrict__ Bv,
    float* __restrict__ C, int K, int Ncols)
{
    __shared__ __align__(16) float As[2][8][128];
    __shared__ __align__(16) float Bs[2][8][128];
    const int tid = threadIdx.x;
    const int rowBase = blockIdx.x * 128;
    const int colBase = blockIdx.y * 128;
    const int ty = tid >> 4, tx = tid & 15;
    unsigned long long acc[8][4];
#pragma unroll
    for (int i = 0; i < 8; i++)
#pragma unroll
        for (int j = 0; j < 4; j++) acc[i][j] = 0ull;

    const int aRow = rowBase + (tid >> 1);
    const int aK4 = (tid & 1) * 4;
    const int bCol = colBase + (tid & 31) * 4;
    const int bK = tid >> 5;

    // load tile 0
    float4 av = make_float4(0.f, 0.f, 0.f, 0.f);
    float4 bv = make_float4(0.f, 0.f, 0.f, 0.f);
    {
        int ka = aK4;
        if (ka < K) {
            if (ka < d1) av = *(const float4*)(A1 + (size_t)aRow * d1 + ka);
            else av = *(const float4*)(A2 + (size_t)aRow * d2 + (ka - d1));
        }
        int kb = bK;
        if (kb < K) bv = *(const float4*)(W + (size_t)kb * Ncols + bCol);
    }
    As[0][aK4 + 0][tid >> 1] = av.x;
    As[0][aK4 + 1][tid >> 1] = av.y;
    As[0][aK4 + 2][tid >> 1] = av.z;
    As[0][aK4 + 3][tid >> 1] = av.w;
    *(float4*)&Bs[0][bK][(tid & 31) * 4] = bv;
    __syncthreads();

    int buf = 0;
    for (int k0 = 0; k0 < K; k0 += 8) {
        const bool more = (k0 + 8 < K);
        // prefetch next tile into registers (in flight during compute)
        if (more) {
            av = make_float4(0.f, 0.f, 0.f, 0.f);
            bv = make_float4(0.f, 0.f, 0.f, 0.f);
            int ka = k0 + 8 + aK4;
            if (ka < K) {
                if (ka < d1) av = *(const float4*)(A1 + (size_t)aRow * d1 + ka);
                else av = *(const float4*)(A2 + (size_t)aRow * d2 + (ka - d1));
            }
            int kb = k0 + 8 + bK;
            if (kb < K) bv = *(const float4*)(W + (size_t)kb * Ncols + bCol);
        }
#pragma unroll
        for (int kk = 0; kk < 8; kk++) {
            float4 a0 = *(const float4*)&As[buf][kk][ty * 8];
            float4 a1 = *(const float4*)&As[buf][kk][ty * 8 + 4];
            // conflict-free: chunks tx and tx+16 -> distinct bank-quads per 8-lane phase
            float4 b0 = *(const float4*)&Bs[buf][kk][tx * 4];
            float4 b1 = *(const float4*)&Bs[buf][kk][64 + tx * 4];
            unsigned long long bp0 = pk(b0.x, b0.y), bp1 = pk(b0.z, b0.w);
            unsigned long long bp2 = pk(b1.x, b1.y), bp3 = pk(b1.z, b1.w);
            float ar[8] = {a0.x, a0.y, a0.z, a0.w, a1.x, a1.y, a1.z, a1.w};
#pragma unroll
            for (int i = 0; i < 8; i++) {
                unsigned long long a2 = pk(ar[i], ar[i]);
                ffma2(acc[i][0], a2, bp0);
                ffma2(acc[i][1], a2, bp1);
                ffma2(acc[i][2], a2, bp2);
                ffma2(acc[i][3], a2, bp3);
            }
        }
        if (more) {
            int nb = buf ^ 1;
            As[nb][aK4 + 0][tid >> 1] = av.x;
            As[nb][aK4 + 1][tid >> 1] = av.y;
            As[nb][aK4 + 2][tid >> 1] = av.z;
            As[nb][aK4 + 3][tid >> 1] = av.w;
            *(float4*)&Bs[nb][bK][(tid & 31) * 4] = bv;
            __syncthreads();
            buf = nb;
        }
    }
    // epilogue: cols [colBase+tx*4, +4) and [colBase+64+tx*4, +4)
    float bias[8];
#pragma unroll
    for (int j = 0; j < 4; j++) bias[j] = Bv[colBase + tx * 4 + j];
#pragma unroll
    for (int j = 0; j < 4; j++) bias[4 + j] = Bv[colBase + 64 + tx * 4 + j];
#pragma unroll
    for (int i = 0; i < 8; i++) {
        int row = rowBase + ty * 8 + i;
        float o[8];
#pragma unroll
        for (int j = 0; j < 4; j++) upk(acc[i][j], o[j * 2], o[j * 2 + 1]);
#pragma unroll
        for (int j = 0; j < 8; j++) o[j] = eluf(o[j] + bias[j]);
        *(float4*)(C + (size_t)row * Ncols + colBase + tx * 4) = make_float4(o[0], o[1], o[2], o[3]);
        *(float4*)(C + (size_t)row * Ncols + colBase + 64 + tx * 4) = make_float4(o[4], o[5], o[6], o[7]);
    }
}

// ---------------- z head + VQ + distance matrix emit (column-major) ----------------
__global__ void __launch_bounds__(256) zvq_kernel(
    const float* __restrict__ W3, const float* __restrict__ b3,
    const float* __restrict__ emb, float* __restrict__ qOut, float* __restrict__ idxOut)
{
    __shared__ __align__(16) float WsT[16 * 256];
    __shared__ __align__(16) float EsT[16 * 256];
    __shared__ float b3s[16];
    __shared__ float zsh[8][16];
    __shared__ float dstage[256][9]; // [code][warp], padded to kill bank conflicts
    __shared__ double blkAcc;
    int tid = threadIdx.x;
    for (int i = tid; i < 4096; i += 256) { int k = i >> 4, j = i & 15; WsT[j * 256 + k] = W3[i]; }
    for (int i = tid; i < 4096; i += 256) EsT[i] = g_nembT[i];
    if (tid < 16) b3s[tid] = b3[tid];
    if (tid == 0) blkAcc = 0.0;
    __syncthreads();

    int warp = tid >> 5, lane = tid & 31;
    size_t row = (size_t)blockIdx.x * 8 + warp;
    const float4* hr = (const float4*)(g_h2 + row * 256);
    float4 h0 = hr[lane * 2], h1v = hr[lane * 2 + 1];
    float hv[8] = {h0.x, h0.y, h0.z, h0.w, h1v.x, h1v.y, h1v.z, h1v.w};
    float z[16];
#pragma unroll
    for (int j = 0; j < 16; j++) {
        const float* wj = &WsT[j * 256 + lane * 8];
        float s = 0.f;
#pragma unroll
        for (int kk = 0; kk < 8; kk++) s = fmaf(hv[kk], wj[kk], s);
        z[j] = s;
    }
#pragma unroll
    for (int off = 16; off > 0; off >>= 1)
#pragma unroll
        for (int j = 0; j < 16; j++) z[j] += __shfl_xor_sync(0xffffffffu, z[j], off);
    float ss = 0.f;
#pragma unroll
    for (int j = 0; j < 16; j++) { z[j] += b3s[j]; ss = fmaf(z[j], z[j], ss); }
    float rinv = 1.0f / fmaxf(sqrtf(ss), 1e-12f);
    float zn[16];
#pragma unroll
    for (int j = 0; j < 16; j++) zn[j] = z[j] * rinv;

    float simv[8];
    float best = -3.0e38f; int bidx = 0x7fffffff;
#pragma unroll
    for (int cc = 0; cc < 8; cc++) {
        int c = cc * 32 + lane;
        float s = 0.f;
#pragma unroll
        for (int j = 0; j < 16; j++) s = fmaf(zn[j], EsT[j * 256 + c], s);
        simv[cc] = s;
        if (s > best) { best = s; bidx = c; }
    }
#pragma unroll
    for (int cc = 0; cc < 8; cc++) dstage[cc * 32 + lane][warp] = simv[cc];
#pragma unroll
    for (int off = 16; off > 0; off >>= 1) {
        float ov = __shfl_xor_sync(0xffffffffu, best, off);
        int oi = __shfl_xor_sync(0xffffffffu, bidx, off);
        if (ov > best || (ov == best && oi < bidx)) { best = ov; bidx = oi; }
    }
    bidx = __shfl_sync(0xffffffffu, bidx, 0);
    if (lane == 0) {
        idxOut[row] = (float)bidx;
        atomicAdd(&g_counts[bidx], 1u);
#pragma unroll
        for (int j = 0; j < 16; j++) zsh[warp][j] = z[j];
    }
    __syncwarp();
    float dv = 0.f;
    if (lane < 16) {
        float q = emb[bidx * 16 + lane];
        qOut[row * 16 + lane] = q;
        float d = q - zsh[warp][lane];
        dv = d * d;
    }
#pragma unroll
    for (int off = 16; off > 0; off >>= 1) dv += __shfl_xor_sync(0xffffffffu, dv, off);
    if (lane == 0) atomicAdd(&blkAcc, (double)dv);
    __syncthreads();
    // write distances column-major: thread tid = code, 8 rows of this block
    {
        int c = tid;
        size_t row0 = (size_t)blockIdx.x * 8;
        float v[8];
#pragma unroll
        for (int i = 0; i < 8; i++) v[i] = dstage[c][i];
        float* dst = g_dist + (size_t)c * NR + row0;
        *(float4*)dst = make_float4(v[0], v[1], v[2], v[3]);
        *(float4*)(dst + 4) = make_float4(v[4], v[5], v[6], v[7]);
    }
    if (tid == 0) atomicAdd(&g_acc[0], blkAcc);
}

// ---------------- pass A: per-code histogram, grid (256 codes, 4 segments) ----------------
__global__ void __launch_bounds__(256) hist_kernel() {
    __shared__ unsigned int hist[NBINS];
    int k = blockIdx.x, tid = threadIdx.x;
    for (int i = tid; i < NBINS; i += 256) hist[i] = 0u;
    __syncthreads();
    const float4* col = (const float4*)(g_dist + (size_t)k * NR + (size_t)blockIdx.y * (NR / 4));
    for (int i = tid; i < NR / 16; i += 256) {
        float4 v = col[i];
        atomicAdd(&hist[bin_of(v.x)], 1u);
        atomicAdd(&hist[bin_of(v.y)], 1u);
        atomicAdd(&hist[bin_of(v.z)], 1u);
        atomicAdd(&hist[bin_of(v.w)], 1u);
    }
    __syncthreads();
    for (int i = tid; i < NBINS; i += 256) {
        unsigned int h = hist[i];
        if (h) atomicAdd(&g_hist[k * NBINS + i], h);
    }
}

// ---------------- scan: thresholds ----------------
__global__ void __launch_bounds__(256) scan_kernel() {
    int k = blockIdx.x, tid = threadIdx.x;
    __shared__ unsigned int csum[256];
    unsigned int s = 0;
#pragma unroll
    for (int i = 0; i < 8; i++) s += g_hist[k * NBINS + tid * 8 + i];
    csum[tid] = s;
    __syncthreads();
    if (tid == 0) {
        unsigned int cum = 0; int bb = NBINS - 1; unsigned int cbelow = 0; bool done = false;
        for (int c = 0; c < 256 && !done; c++) {
            if (cum + csum[c] >= 65536u) {
                unsigned int c2 = cum;
                for (int b = c * 8; b < c * 8 + 8; b++) {
                    unsigned int h = g_hist[k * NBINS + b];
                    if (c2 + h >= 65536u) { bb = b; cbelow = c2; done = true; break; }
                    c2 += h;
                }
            } else cum += csum[c];
        }
        unsigned int cumt = 0; int bt = 0; unsigned int cabove = 0; done = false;
        for (int c = 255; c >= 0 && !done; c--) {
            if (cumt + csum[c] >= 512u) {
                unsigned int c2 = cumt;
                for (int b = c * 8 + 7; b >= c * 8; b--) {
                    unsigned int h = g_hist[k * NBINS + b];
                    if (c2 + h >= 512u) { bt = b; cabove = c2; done = true; break; }
                    c2 += h;
                }
            } else cumt += csum[c];
        }
        g_thr[k * 4 + 0] = bt; g_thr[k * 4 + 1] = bb;
        g_thr[k * 4 + 2] = (int)cabove; g_thr[k * 4 + 3] = (int)cbelow;
    }
}

// ---------------- pass B: sums + critical-bin gather, grid (256, 4) ----------------
__global__ void __launch_bounds__(256) passB_kernel() {
    __shared__ double dred[256];
    int k = blockIdx.x, tid = threadIdx.x;
    int bt = g_thr[k * 4 + 0], bb = g_thr[k * 4 + 1];
    float ref = bin_low(bt);
    double sexp = 0.0, stp = 0.0;
    const float4* col = (const float4*)(g_dist + (size_t)k * NR + (size_t)blockIdx.y * (NR / 4));
    for (int i = tid; i < NR / 16; i += 256) {
        float4 v4 = col[i];
        float vs[4] = {v4.x, v4.y, v4.z, v4.w};
#pragma unroll
        for (int e = 0; e < 4; e++) {
            float s = vs[e];
            int bin = bin_of(s);
            if (bin < bb) {
                sexp += (double)expf((s - ref) * (1.0f / 0.07f));
            } else if (bin == bb) {
                unsigned int p = atomicAdd(&g_botcnt[k], 1u);
                if (p < CAP) g_botbuf[(size_t)k * CAP + p] = s;
            }
            if (bin > bt) {
                stp += (double)s;
            } else if (bin == bt) {
                unsigned int p = atomicAdd(&g_topcnt[k], 1u);
                if (p < CAP) g_topbuf[(size_t)k * CAP + p] = s;
            }
        }
    }
    dred[tid] = sexp; __syncthreads();
    for (int s2 = 128; s2 > 0; s2 >>= 1) { if (tid < s2) dred[tid] += dred[tid + s2]; __syncthreads(); }
    if (tid == 0) atomicAdd(&g_sumexp[k], dred[0]);
    __syncthreads();
    dred[tid] = stp; __syncthreads();
    for (int s2 = 128; s2 > 0; s2 >>= 1) { if (tid < s2) dred[tid] += dred[tid + s2]; __syncthreads(); }
    if (tid == 0) atomicAdd(&g_sumtop[k], dred[0]);
}

// ---------------- finalize: rank-select in critical bins, contra per code ----------------
__global__ void __launch_bounds__(256) finalize_kernel() {
    __shared__ float sbuf[CAP];
    __shared__ double dred[256];
    __shared__ double sh_dispos;
    int k = blockIdx.x, tid = threadIdx.x;
    int bt = g_thr[k * 4 + 0], ca = g_thr[k * 4 + 2], cb = g_thr[k * 4 + 3];
    float ref = bin_low(bt);

    int tc = min((int)g_topcnt[k], CAP);
    for (int i = tid; i < tc; i += 256) sbuf[i] = g_topbuf[(size_t)k * CAP + i];
    __syncthreads();
    int needt = 512 - ca; if (needt > tc) needt = tc; if (needt < 0) needt = 0;
    double lsum = 0.0;
    for (int i = tid; i < tc; i += 256) {
        float v = sbuf[i]; int r = 0;
        for (int j = 0; j < tc; j++) {
            float u = sbuf[j];
            r += (u > v) || (u == v && j < i);
        }
        if (r < needt) lsum += (double)v;
    }
    dred[tid] = lsum; __syncthreads();
    for (int s2 = 128; s2 > 0; s2 >>= 1) { if (tid < s2) dred[tid] += dred[tid + s2]; __syncthreads(); }
    if (tid == 0) sh_dispos = (g_sumtop[k] + dred[0]) * (1.0 / 512.0);
    __syncthreads();

    int bc = min((int)g_botcnt[k], CAP);
    for (int i = tid; i < bc; i += 256) sbuf[i] = g_botbuf[(size_t)k * CAP + i];
    __syncthreads();
    int needb = 65536 - cb; if (needb > bc) needb = bc; if (needb < 0) needb = 0;
    lsum = 0.0;
    for (int i = tid; i < bc; i += 256) {
        float v = sbuf[i]; int r = 0;
        for (int j = 0; j < bc; j++) {
            float u = sbuf[j];
            r += (u < v) || (u == v && j < i);
        }
        if (r < needb) lsum += (double)expf((v - ref) * (1.0f / 0.07f));
    }
    dred[tid] = lsum; __syncthreads();
    for (int s2 = 128; s2 > 0; s2 >>= 1) { if (tid < s2) dred[tid] += dred[tid + s2]; __syncthreads(); }
    if (tid == 0) {
        double S = (g_sumexp[k] + dred[0]) * exp(((double)ref - sh_dispos) * (1.0 / 0.07));
        atomicAdd(&g_acc[2], log1p(S));
    }
}

// ---------------- dec3 (512 -> 12) + recon loss ----------------
__global__ void __launch_bounds__(256) dec3_kernel(
    const float* __restrict__ W, const float* __restrict__ Bv,
    const float* __restrict__ actions, float* __restrict__ recOut)
{
    __shared__ __align__(16) float WsT[12][512];
    __shared__ float bs[12];
    __shared__ float rsh[8][12];
    __shared__ double blkAcc;
    int tid = threadIdx.x;
    for (int i = tid; i < 6144; i += 256) { int kk = i / 12, j = i % 12; WsT[j][kk] = W[i]; }
    if (tid < 12) bs[tid] = Bv[tid];
    if (tid == 0) blkAcc = 0.0;
    __syncthreads();
    int warp = tid >> 5, lane = tid & 31;
    size_t row = (size_t)blockIdx.x * 8 + warp;
    const float4* hp = (const float4*)(g_h1 + row * 512);
    float4 hq[4];
#pragma unroll
    for (int q = 0; q < 4; q++) hq[q] = hp[lane * 4 + q];
    float hv[16] = {hq[0].x, hq[0].y, hq[0].z, hq[0].w, hq[1].x, hq[1].y, hq[1].z, hq[1].w,
                    hq[2].x, hq[2].y, hq[2].z, hq[2].w, hq[3].x, hq[3].y, hq[3].z, hq[3].w};
#pragma unroll
    for (int j = 0; j < 12; j++) {
        const float* wj = &WsT[j][lane * 16];
        float s = 0.f;
#pragma unroll
        for (int kk = 0; kk < 16; kk++) s = fmaf(hv[kk], wj[kk], s);
#pragma unroll
        for (int off = 16; off > 0; off >>= 1) s += __shfl_xor_sync(0xffffffffu, s, off);
        if (lane == 0) rsh[warp][j] = s + bs[j];
    }
    __syncwarp();
    float dv = 0.f;
    if (lane < 12) {
        float rec = rsh[warp][lane];
        recOut[row * 12 + lane] = rec;
        float d = rec - actions[row * 12 + lane];
        dv = d * d;
    }
#pragma unroll
    for (int off = 16; off > 0; off >>= 1) dv += __shfl_xor_sync(0xffffffffu, dv, off);
    if (lane == 0) atomicAdd(&blkAcc, (double)dv);
    __syncthreads();
    if (tid == 0) atomicAdd(&g_acc[1], blkAcc);
}

// ---------------- final scalars ----------------
__global__ void final_kernel(float* __restrict__ scal) {
    __shared__ double red[256];
    int t = threadIdx.x;
    double p = (double)g_counts[t] / 131072.0;
    red[t] = p * log(p + 1e-10);
    __syncthreads();
    for (int s = 128; s > 0; s >>= 1) { if (t < s) red[t] += red[t + s]; __syncthreads(); }
    if (t == 0) {
        double q = g_acc[0] / (131072.0 * 16.0);
        scal[0] = (float)q;                               // q_latent_loss
        scal[1] = (float)(0.25 * q);                      // e_latent_loss
        scal[2] = (float)(g_acc[2] / 256.0);              // contra_loss
        scal[3] = (float)exp(-red[0]);                    // perplexity
        scal[4] = (float)(g_acc[1] / (131072.0 * 12.0));  // reconstruction_loss
    }
}

// ---------------- launch ----------------
extern "C" void kernel_launch(void* const* d_in, const int* in_sizes, int n_in,
                              void* d_out, int out_size)
{
    const float* actions = (const float*)d_in[0];
    const float* conditions = (const float*)d_in[1];
    const float* enc_w1 = (const float*)d_in[2];
    const float* enc_b1 = (const float*)d_in[3];
    const float* enc_w2 = (const float*)d_in[4];
    const float* enc_b2 = (const float*)d_in[5];
    const float* enc_w3 = (const float*)d_in[6];
    const float* enc_b3 = (const float*)d_in[7];
    const float* dec_w1 = (const float*)d_in[8];
    const float* dec_b1 = (const float*)d_in[9];
    const float* dec_w2 = (const float*)d_in[10];
    const float* dec_b2 = (const float*)d_in[11];
    const float* dec_w3 = (const float*)d_in[12];
    const float* dec_b3 = (const float*)d_in[13];
    const float* embedding = (const float*)d_in[14];

    float* out = (float*)d_out;
    float* recon = out;                       // N*12
    float* quant = out + (size_t)NR * 12;     // N*16
    float* idxf  = out + (size_t)NR * 28;     // N
    float* scal  = out + (size_t)NR * 29;     // 5 scalars

    float *h1p, *h2p;
    cudaGetSymbolAddress((void**)&h1p, g_h1);
    cudaGetSymbolAddress((void**)&h2p, g_h2);

    zero_kernel<<<2048, 256>>>();
    norm_emb_kernel<<<1, 256>>>(embedding);
    // enc1: [actions|conditions](268) @ enc_w1 -> h1 (N x 512)
    gemm_bias_elu<<<dim3(NR / 128, 4), 256>>>(actions, 12, conditions, 256, enc_w1, enc_b1, h1p, 268, 512);
    // enc2: h1(512) @ enc_w2 -> h2 (N x 256)
    gemm_bias_elu<<<dim3(NR / 128, 2), 256>>>(h1p, 512, h1p, 0, enc_w2, enc_b2, h2p, 512, 256);
    // z head + VQ + dist emit
    zvq_kernel<<<NR / 8, 256>>>(enc_w3, enc_b3, embedding, quant, idxf);
    // contra stats (streaming over stored distances)
    hist_kernel<<<dim3(256, 4), 256>>>();
    scan_kernel<<<256, 256>>>();
    passB_kernel<<<dim3(256, 4), 256>>>();
    finalize_kernel<<<256, 256>>>();
    // dec1: [quant|conditions](272) @ dec_w1 -> h2 (N x 256)
    gemm_bias_elu<<<dim3(NR / 128, 2), 256>>>(quant, 16, conditions, 256, dec_w1, dec_b1, h2p, 272, 256);
    // dec2: h2(256) @ dec_w2 -> h1 (N x 512)
    gemm_bias_elu<<<dim3(NR / 128, 4), 256>>>(h2p, 256, h2p, 0, dec_w2, dec_b2, h1p, 256, 512);
    // dec3 + recon loss
    dec3_kernel<<<NR / 8, 256>>>(dec_w3, dec_b3, actions, recon);
    // scalars
    final_kernel<<<1, 256>>>(scal);
}